// round 4
// baseline (speedup 1.0000x reference)
#include <cuda_runtime.h>
#include <math.h>

#define CO   256
#define HW   128
#define NB   16

// ---------------- device scratch (no allocations allowed) ----------------
__device__ float g_y[(size_t)NB * CO * HW * HW];        // 268 MB intermediate
__device__ float g_bank1[4 * 128 * 9 * CO];             // [k][ci][tap][co]
__device__ float g_bank2[4 * 256 * 9 * CO];
__device__ float g_gap[NB * 256];
__device__ float g_attn[NB * 4];

// ---------------- irfft2 synthesis: 12 reals -> 9 spatial taps ----------------
// jnp.fft.irfft2(Fr + i Fi, s=(3,3)):
//   G[y,kx]  = sum_ky F[ky,kx] * e^{+2*pi*i*ky*y/3}          (ifft along -2, 1/3 folded later)
//   w[y,x]   = (Re G[y,0] + 2*(Re G[y,1]*cos(2pi x/3) - Im G[y,1]*sin(2pi x/3))) / 9
// (c2r drops Im of bin 0.)
__global__ void synth_kernel(const float* __restrict__ fr, const float* __restrict__ fi,
                             float* __restrict__ bank, int Ci) {
    int idx = blockIdx.x * blockDim.x + threadIdx.x;
    int total = 4 * CO * Ci;
    if (idx >= total) return;
    int ci = idx % Ci;
    int t  = idx / Ci;
    int co = t % CO;
    int k  = t / CO;

    const float* pr = fr + (size_t)idx * 6;   // layout [K][Co][Ci][3][2] contiguous
    const float* pi = fi + (size_t)idx * 6;
    float Fr[3][2], Fi[3][2];
#pragma unroll
    for (int a = 0; a < 3; a++)
#pragma unroll
        for (int x2 = 0; x2 < 2; x2++) {
            Fr[a][x2] = pr[a * 2 + x2];
            Fi[a][x2] = pi[a * 2 + x2];
        }

    const float Hs = 0.86602540378443864676f;           // sqrt(3)/2
    const float cm[3] = { 1.f, -0.5f, -0.5f };          // cos(2*pi*m/3)
    const float sm[3] = { 0.f,  Hs,   -Hs  };           // sin(2*pi*m/3)

    float* outp = bank + ((size_t)(k * Ci + ci) * 9) * CO + co;

#pragma unroll
    for (int y = 0; y < 3; y++) {
        float Gr0 = 0.f, Gr1 = 0.f, Gi1 = 0.f;
#pragma unroll
        for (int ky = 0; ky < 3; ky++) {
            int m = (ky * y) % 3;
            float c = cm[m], s = sm[m];
            Gr0 += Fr[ky][0] * c - Fi[ky][0] * s;
            Gr1 += Fr[ky][1] * c - Fi[ky][1] * s;
            Gi1 += Fr[ky][1] * s + Fi[ky][1] * c;
        }
#pragma unroll
        for (int xx = 0; xx < 3; xx++) {
            float w = (Gr0 + 2.f * (Gr1 * cm[xx] - Gi1 * sm[xx])) * (1.f / 9.f);
            outp[(y * 3 + xx) * CO] = w;
        }
    }
}

// ---------------- global average pool: one block per (b, c) ----------------
__global__ void gap_kernel(const float* __restrict__ in, float* __restrict__ gap) {
    const float4* p = reinterpret_cast<const float4*>(in + (size_t)blockIdx.x * (HW * HW));
    float s = 0.f;
    for (int i = threadIdx.x; i < HW * HW / 4; i += 256) {
        float4 v = p[i];
        s += (v.x + v.y) + (v.z + v.w);
    }
    __shared__ float red[8];
    for (int o = 16; o; o >>= 1) s += __shfl_down_sync(0xffffffffu, s, o);
    if ((threadIdx.x & 31) == 0) red[threadIdx.x >> 5] = s;
    __syncthreads();
    if (threadIdx.x < 8) {
        s = red[threadIdx.x];
        for (int o = 4; o; o >>= 1) s += __shfl_down_sync(0xffu, s, o);
        if (threadIdx.x == 0) gap[blockIdx.x] = s * (1.f / (HW * HW));
    }
}

// ---------------- GAP -> MLP -> softmax attention, one block per sample ----------------
__global__ void attn_kernel(const float* __restrict__ gap, const float* __restrict__ w1,
                            const float* __restrict__ b1, const float* __restrict__ w2,
                            const float* __restrict__ b2, float* __restrict__ attn,
                            int C, int Hd) {
    __shared__ float gs[256];
    __shared__ float hbuf[64];
    int b = blockIdx.x;
    for (int i = threadIdx.x; i < C; i += blockDim.x) gs[i] = gap[b * C + i];
    __syncthreads();
    for (int j = threadIdx.x; j < Hd; j += blockDim.x) {
        float s = b1[j];
        for (int c = 0; c < C; c++) s += gs[c] * w1[c * Hd + j];
        hbuf[j] = fmaxf(s, 0.f);
    }
    __syncthreads();
    if (threadIdx.x == 0) {
        float l[4];
        float m = -1e30f;
        for (int k = 0; k < 4; k++) {
            float s = b2[k];
            for (int j = 0; j < Hd; j++) s += hbuf[j] * w2[j * 4 + k];
            l[k] = s;
            m = fmaxf(m, s);
        }
        float sum = 0.f;
        for (int k = 0; k < 4; k++) { l[k] = expf(l[k] - m); sum += l[k]; }
        float inv = 1.f / sum;
        for (int k = 0; k < 4; k++) attn[b * 4 + k] = l[k] * inv;
    }
}

// ---------------- dynamic 3x3 conv + bias + relu ----------------
// Block: 256 thr (tx=lane 0..31, ty 0..7). Tile: 32x32 spatial, 8 co, ci in chunks of 8.
// Per thread: 4 pixels (rows ty, ty+8, ty+16, ty+24) as 2 f32x2 pixel-pairs x 8 co accumulators.
// Weights mixed per-sample from 4-kernel bank into smem as duplicated float2 {w,w}
// so a broadcast LDS.64 feeds fma.rn.f32x2 directly.
template<int CIN>
__global__ void __launch_bounds__(256, 2)
conv_fd_kernel(const float* __restrict__ x, const float* __restrict__ bank,
               const float* __restrict__ attn, const float* __restrict__ bias,
               float* __restrict__ out) {
    __shared__ float  sx[8][34 * 34 + 2];
    __shared__ float2 sw[8][9][8];

    const int tid = threadIdx.x;
    const int tx = tid & 31, ty = tid >> 5;
    const int b   = blockIdx.z;
    const int co0 = blockIdx.y * 8;
    const int y0  = (blockIdx.x >> 2) * 32;
    const int x0  = (blockIdx.x & 3) * 32;

    const float a0 = attn[b * 4 + 0], a1 = attn[b * 4 + 1];
    const float a2 = attn[b * 4 + 2], a3 = attn[b * 4 + 3];
    const int plane = CIN * 9 * CO;

    unsigned long long acc[2][8];
#pragma unroll
    for (int p = 0; p < 2; p++)
#pragma unroll
        for (int c = 0; c < 8; c++) acc[p][c] = 0ULL;

    const float* xb = x + (size_t)b * CIN * HW * HW;

    for (int ci0 = 0; ci0 < CIN; ci0 += 8) {
        __syncthreads();
        // stage x halo tile (34x34 per ci plane), zero-padded at image borders
        for (int i = tid; i < 8 * 34 * 34; i += 256) {
            int ci = i / (34 * 34);
            int r  = i - ci * (34 * 34);
            int ly = r / 34, lx = r - ly * 34;
            int gy = y0 - 1 + ly, gx = x0 - 1 + lx;
            float v = 0.f;
            if ((unsigned)gy < 128u && (unsigned)gx < 128u)
                v = xb[((ci0 + ci) * HW + gy) * HW + gx];
            sx[ci][r] = v;
        }
        // mix per-sample weights: wd = sum_k attn[k] * bank[k]
        for (int i = tid; i < 8 * 9 * 8; i += 256) {
            int ci  = i / 72;
            int r   = i - ci * 72;
            int tap = r >> 3;
            int col = r & 7;
            int base = ((ci0 + ci) * 9 + tap) * CO + co0 + col;
            float v = a0 * bank[base] + a1 * bank[base + plane]
                    + a2 * bank[base + 2 * plane] + a3 * bank[base + 3 * plane];
            sw[ci][tap][col] = make_float2(v, v);
        }
        __syncthreads();

#pragma unroll 2
        for (int ci = 0; ci < 8; ci++) {
            const float* sp = sx[ci];
#pragma unroll
            for (int p2 = 0; p2 < 2; p2++) {
                const int rA = ty + 16 * p2;   // pixel pair rows rA, rA+8
                const int rB = rA + 8;
                unsigned long long xq[9];
#pragma unroll
                for (int dy = 0; dy < 3; dy++)
#pragma unroll
                    for (int dx = 0; dx < 3; dx++) {
                        float va = sp[(rA + dy) * 34 + tx + dx];
                        float vb = sp[(rB + dy) * 34 + tx + dx];
                        asm("mov.b64 %0, {%1, %2};" : "=l"(xq[dy * 3 + dx]) : "f"(va), "f"(vb));
                    }
#pragma unroll
                for (int t = 0; t < 9; t++) {
                    const unsigned long long* wrow =
                        reinterpret_cast<const unsigned long long*>(&sw[ci][t][0]);
#pragma unroll
                    for (int c = 0; c < 8; c++) {
                        unsigned long long w2 = wrow[c];   // broadcast LDS.64 {w,w}
                        asm("fma.rn.f32x2 %0, %1, %2, %0;"
                            : "+l"(acc[p2][c]) : "l"(w2), "l"(xq[t]));
                    }
                }
            }
        }
    }

    // epilogue: bias + relu + store
#pragma unroll
    for (int c = 0; c < 8; c++) {
        float bv = bias[co0 + c];
        float* ob = out + (size_t)(b * CO + co0 + c) * HW * HW;
#pragma unroll
        for (int p2 = 0; p2 < 2; p2++) {
            float va, vb;
            asm("mov.b64 {%0, %1}, %2;" : "=f"(va), "=f"(vb) : "l"(acc[p2][c]));
            int oyA = y0 + ty + 16 * p2;
            va = fmaxf(va + bv, 0.f);
            vb = fmaxf(vb + bv, 0.f);
            ob[oyA * HW + x0 + tx]       = va;
            ob[(oyA + 8) * HW + x0 + tx] = vb;
        }
    }
}

// ---------------- launch ----------------
extern "C" void kernel_launch(void* const* d_in, const int* in_sizes, int n_in,
                              void* d_out, int out_size) {
    const float* x    = (const float*)d_in[0];
    const float* w1fr = (const float*)d_in[1];
    const float* w1fi = (const float*)d_in[2];
    const float* b1   = (const float*)d_in[3];
    const float* a1w1 = (const float*)d_in[4];
    const float* a1b1 = (const float*)d_in[5];
    const float* a1w2 = (const float*)d_in[6];
    const float* a1b2 = (const float*)d_in[7];
    const float* w2fr = (const float*)d_in[8];
    const float* w2fi = (const float*)d_in[9];
    const float* b2   = (const float*)d_in[10];
    const float* a2w1 = (const float*)d_in[11];
    const float* a2b1 = (const float*)d_in[12];
    const float* a2w2 = (const float*)d_in[13];
    const float* a2b2 = (const float*)d_in[14];
    float* out = (float*)d_out;

    float *yb, *bank1, *bank2, *gapb, *attnb;
    cudaGetSymbolAddress((void**)&yb,    g_y);
    cudaGetSymbolAddress((void**)&bank1, g_bank1);
    cudaGetSymbolAddress((void**)&bank2, g_bank2);
    cudaGetSymbolAddress((void**)&gapb,  g_gap);
    cudaGetSymbolAddress((void**)&attnb, g_attn);

    // synthesize spatial kernel banks (data-independent of x, cheap)
    synth_kernel<<<(4 * CO * 128 + 255) / 256, 256>>>(w1fr, w1fi, bank1, 128);
    synth_kernel<<<(4 * CO * 256 + 255) / 256, 256>>>(w2fr, w2fi, bank2, 256);

    // layer 1
    gap_kernel<<<NB * 128, 256>>>(x, gapb);
    attn_kernel<<<NB, 64>>>(gapb, a1w1, a1b1, a1w2, a1b2, attnb, 128, 32);
    conv_fd_kernel<128><<<dim3(16, CO / 8, NB), 256>>>(x, bank1, attnb, b1, yb);

    // layer 2
    gap_kernel<<<NB * 256, 256>>>(yb, gapb);
    attn_kernel<<<NB, 64>>>(gapb, a2w1, a2b1, a2w2, a2b2, attnb, 256, 64);
    conv_fd_kernel<256><<<dim3(16, CO / 8, NB), 256>>>(yb, bank2, attnb, b2, out);
}

// round 6
// speedup vs baseline: 6.6335x; 6.6335x over previous
#include <cuda_runtime.h>
#include <cuda_fp16.h>
#include <math.h>
#include <stdint.h>

#define CO   256
#define HW   128
#define NB   16

// ---------------- device scratch ----------------
__device__ float  g_y[(size_t)NB * CO * HW * HW];                 // layer-1 output
__device__ float  g_bank1[4 * 256 * 128 * 9];                     // [kb][co][ci*9+tap]
__device__ float  g_bank2[4 * 256 * 256 * 9];
__device__ __align__(16) __half g_wmix1[(size_t)NB * CO * 128 * 9];   // [b][co][K]
__device__ __align__(16) __half g_wmix2[(size_t)NB * CO * 256 * 9];
__device__ float  g_gap[NB * 256];
__device__ float  g_attn[NB * 4];

// ---------------- PTX helpers (base sm_103-safe only) ----------------
__device__ __forceinline__ uint32_t smem_u32(const void* p) {
    uint32_t a;
    asm("{ .reg .u64 t; cvta.to.shared.u64 t, %1; cvt.u32.u64 %0, t; }" : "=r"(a) : "l"(p));
    return a;
}
__device__ __forceinline__ void ldsm_x4(uint32_t& r0, uint32_t& r1, uint32_t& r2, uint32_t& r3,
                                        uint32_t addr) {
    asm volatile("ldmatrix.sync.aligned.m8n8.x4.shared.b16 {%0,%1,%2,%3}, [%4];"
                 : "=r"(r0), "=r"(r1), "=r"(r2), "=r"(r3) : "r"(addr));
}
__device__ __forceinline__ void ldsm_x4_t(uint32_t& r0, uint32_t& r1, uint32_t& r2, uint32_t& r3,
                                          uint32_t addr) {
    asm volatile("ldmatrix.sync.aligned.m8n8.x4.trans.shared.b16 {%0,%1,%2,%3}, [%4];"
                 : "=r"(r0), "=r"(r1), "=r"(r2), "=r"(r3) : "r"(addr));
}
__device__ __forceinline__ void mma16816(float* d, const uint32_t* a, uint32_t b0, uint32_t b1) {
    asm volatile("mma.sync.aligned.m16n8k16.row.col.f32.f16.f16.f32 "
                 "{%0,%1,%2,%3}, {%4,%5,%6,%7}, {%8,%9}, {%0,%1,%2,%3};"
                 : "+f"(d[0]), "+f"(d[1]), "+f"(d[2]), "+f"(d[3])
                 : "r"(a[0]), "r"(a[1]), "r"(a[2]), "r"(a[3]), "r"(b0), "r"(b1));
}

// ---------------- irfft2 synthesis into bank [kb][co][ci*9+tap] ----------------
__global__ void synth_kernel(const float* __restrict__ fr, const float* __restrict__ fi,
                             float* __restrict__ bank, int Ci) {
    int idx = blockIdx.x * blockDim.x + threadIdx.x;
    int total = 4 * CO * Ci;
    if (idx >= total) return;
    int ci = idx % Ci;
    int t  = idx / Ci;   // kb*CO + co

    const float* pr = fr + (size_t)idx * 6;
    const float* pi = fi + (size_t)idx * 6;
    float Fr[3][2], Fi[3][2];
#pragma unroll
    for (int a = 0; a < 3; a++)
#pragma unroll
        for (int x2 = 0; x2 < 2; x2++) {
            Fr[a][x2] = pr[a * 2 + x2];
            Fi[a][x2] = pi[a * 2 + x2];
        }
    const float Hs = 0.86602540378443864676f;
    const float cm[3] = { 1.f, -0.5f, -0.5f };
    const float sm[3] = { 0.f,  Hs,   -Hs  };

    float* outp = bank + ((size_t)t * Ci + ci) * 9;
#pragma unroll
    for (int y = 0; y < 3; y++) {
        float Gr0 = 0.f, Gr1 = 0.f, Gi1 = 0.f;
#pragma unroll
        for (int ky = 0; ky < 3; ky++) {
            int m = (ky * y) % 3;
            float c = cm[m], s = sm[m];
            Gr0 += Fr[ky][0] * c - Fi[ky][0] * s;
            Gr1 += Fr[ky][1] * c - Fi[ky][1] * s;
            Gi1 += Fr[ky][1] * s + Fi[ky][1] * c;
        }
#pragma unroll
        for (int xx = 0; xx < 3; xx++)
            outp[y * 3 + xx] = (Gr0 + 2.f * (Gr1 * cm[xx] - Gi1 * sm[xx])) * (1.f / 9.f);
    }
}

// ---------------- global average pool ----------------
__global__ void gap_kernel(const float* __restrict__ in, float* __restrict__ gap) {
    const float4* p = reinterpret_cast<const float4*>(in + (size_t)blockIdx.x * (HW * HW));
    float s = 0.f;
    for (int i = threadIdx.x; i < HW * HW / 4; i += 256) {
        float4 v = p[i];
        s += (v.x + v.y) + (v.z + v.w);
    }
    __shared__ float red[8];
    for (int o = 16; o; o >>= 1) s += __shfl_down_sync(0xffffffffu, s, o);
    if ((threadIdx.x & 31) == 0) red[threadIdx.x >> 5] = s;
    __syncthreads();
    if (threadIdx.x < 8) {
        s = red[threadIdx.x];
        for (int o = 4; o; o >>= 1) s += __shfl_down_sync(0xffu, s, o);
        if (threadIdx.x == 0) gap[blockIdx.x] = s * (1.f / (HW * HW));
    }
}

// ---------------- GAP -> MLP -> softmax ----------------
__global__ void attn_kernel(const float* __restrict__ gap, const float* __restrict__ w1,
                            const float* __restrict__ b1, const float* __restrict__ w2,
                            const float* __restrict__ b2, float* __restrict__ attn,
                            int C, int Hd) {
    __shared__ float gs[256];
    __shared__ float hbuf[64];
    int b = blockIdx.x;
    for (int i = threadIdx.x; i < C; i += blockDim.x) gs[i] = gap[b * C + i];
    __syncthreads();
    for (int j = threadIdx.x; j < Hd; j += blockDim.x) {
        float s = b1[j];
        for (int c = 0; c < C; c++) s += gs[c] * w1[c * Hd + j];
        hbuf[j] = fmaxf(s, 0.f);
    }
    __syncthreads();
    if (threadIdx.x == 0) {
        float l[4];
        float m = -1e30f;
        for (int k = 0; k < 4; k++) {
            float s = b2[k];
            for (int j = 0; j < Hd; j++) s += hbuf[j] * w2[j * 4 + k];
            l[k] = s; m = fmaxf(m, s);
        }
        float sum = 0.f;
        for (int k = 0; k < 4; k++) { l[k] = expf(l[k] - m); sum += l[k]; }
        float inv = 1.f / sum;
        for (int k = 0; k < 4; k++) attn[b * 4 + k] = l[k] * inv;
    }
}

// ---------------- weight mix: wmix[b][co][k] = sum_kb attn[b][kb]*bank[kb][co][k] ----------
__global__ void mix_kernel(const float* __restrict__ bank, const float* __restrict__ attn,
                           __half* __restrict__ wmix, int K) {
    int total = NB * CO * (K / 2);
    int i = blockIdx.x * blockDim.x + threadIdx.x;
    if (i >= total) return;
    int perb = CO * (K / 2);
    int b = i / perb;
    int r = (i - b * perb) * 2;           // co*K + k
    float a0 = attn[b * 4 + 0], a1 = attn[b * 4 + 1];
    float a2 = attn[b * 4 + 2], a3 = attn[b * 4 + 3];
    int plane = CO * K;
    const float* p = bank + r;
    float x0 = a0 * p[0] + a1 * p[plane] + a2 * p[2 * plane] + a3 * p[3 * plane];
    float x1 = a0 * p[1] + a1 * p[plane + 1] + a2 * p[2 * plane + 1] + a3 * p[3 * plane + 1];
    reinterpret_cast<__half2*>(wmix)[i] = __floats2half2_rn(x0, x1);
}

// ---------------- HMMA implicit-GEMM conv ----------------
// CTA = (b, 128-co half, 2 image rows = 256 px). D[128co][256px], K chunks of 32.
// 512 thr / 16 warps in 4x4: warp tile 32co x 64px = 2x8 m16n8k16 per k16 step.
// Single smem buffer + register-staged gmem pipelining.
#define SA_STRIDE 40          // halves per A row (80B, ldmatrix conflict-free)
#define SB_STRIDE 264         // halves per B row (528B, ldmatrix conflict-free)

template<int CIN>
__global__ void __launch_bounds__(512, 1)
conv_hmma_kernel(const float* __restrict__ x, const __half* __restrict__ wmix,
                 const float* __restrict__ bias, float* __restrict__ out) {
    constexpr int K   = CIN * 9;
    constexpr int NCH = K / 32;

    __shared__ __align__(16) __half sA[128 * SA_STRIDE];   // 10240 B
    __shared__ __align__(16) __half sB[32 * SB_STRIDE];    // 16896 B

    const int tid = threadIdx.x, wid = tid >> 5, lane = tid & 31;
    const int b   = blockIdx.z;
    const int co0 = blockIdx.y * 128;
    const int y0  = blockIdx.x * 2;
    const int wr = wid & 3, wc = wid >> 2;          // warp row (co), warp col (px)

    const float*  xb = x + (size_t)b * CIN * HW * HW;
    const __half* wb = wmix + (size_t)(b * 256 + co0) * K;

    float d[2][8][4];
#pragma unroll
    for (int mt = 0; mt < 2; mt++)
#pragma unroll
        for (int nt = 0; nt < 8; nt++)
#pragma unroll
            for (int q = 0; q < 4; q++) d[mt][nt][q] = 0.f;

    // A staging: thread -> (row=tid>>2, 16B segment=tid&3)
    const int arow = tid >> 2, aseg = tid & 3;
    const __half* aptr = wb + (size_t)arow * K + aseg * 8;
    // B staging: warp handles k-rows 2*wid, 2*wid+1; lane loads float4 per image row
    const int br0 = wid * 2;

    uint4  aS;
    float4 bS[2][2];   // [rsub][yr]

    // ---- load chunk 0 into registers ----
    aS = *reinterpret_cast<const uint4*>(aptr);
#pragma unroll
    for (int rs = 0; rs < 2; rs++) {
        int k = br0 + rs;
        int ci = k / 9, t = k - ci * 9, dy = t / 3;
#pragma unroll
        for (int yr = 0; yr < 2; yr++) {
            int gy = y0 + yr + dy - 1;
            float4 v = make_float4(0.f, 0.f, 0.f, 0.f);
            if ((unsigned)gy < 128u)
                v = __ldg(reinterpret_cast<const float4*>(xb + ((size_t)ci * HW + gy) * HW) + lane);
            bS[rs][yr] = v;
        }
    }

    for (int c = 0; c < NCH; c++) {
        __syncthreads();
        // ---- store staged regs to smem ----
        *reinterpret_cast<uint4*>(sA + arow * SA_STRIDE + aseg * 8) = aS;
#pragma unroll
        for (int rs = 0; rs < 2; rs++) {
            int k = c * 32 + br0 + rs;
            int ci = k / 9, t = k - ci * 9, dx = t % 3;
            __half* base = sB + (br0 + rs) * SB_STRIDE;
#pragma unroll
            for (int yr = 0; yr < 2; yr++) {
                float4 vv = bS[rs][yr];
                float o0, o1, o2, o3;
                if (dx == 1) { o0 = vv.x; o1 = vv.y; o2 = vv.z; o3 = vv.w; }
                else if (dx == 0) {
                    float p = __shfl_up_sync(0xffffffffu, vv.w, 1);
                    if (lane == 0) p = 0.f;
                    o0 = p; o1 = vv.x; o2 = vv.y; o3 = vv.z;
                } else {
                    float nx = __shfl_down_sync(0xffffffffu, vv.x, 1);
                    if (lane == 31) nx = 0.f;
                    o0 = vv.y; o1 = vv.z; o2 = vv.w; o3 = nx;
                }
                __half2 h0 = __floats2half2_rn(o0, o1);
                __half2 h1 = __floats2half2_rn(o2, o3);
                uint2 u;
                u.x = *reinterpret_cast<uint32_t*>(&h0);
                u.y = *reinterpret_cast<uint32_t*>(&h1);
                *reinterpret_cast<uint2*>(base + yr * 128 + lane * 4) = u;
            }
        }
        // ---- issue next chunk's gmem loads (overlap with compute below) ----
        if (c + 1 < NCH) {
            int k0n = (c + 1) * 32;
            aS = *reinterpret_cast<const uint4*>(aptr + k0n);
#pragma unroll
            for (int rs = 0; rs < 2; rs++) {
                int k = k0n + br0 + rs;
                int ci = k / 9, t = k - ci * 9, dy = t / 3;
#pragma unroll
                for (int yr = 0; yr < 2; yr++) {
                    int gy = y0 + yr + dy - 1;
                    float4 v = make_float4(0.f, 0.f, 0.f, 0.f);
                    if ((unsigned)gy < 128u)
                        v = __ldg(reinterpret_cast<const float4*>(xb + ((size_t)ci * HW + gy) * HW) + lane);
                    bS[rs][yr] = v;
                }
            }
        }
        __syncthreads();

        // ---- compute: 2 k16-steps ----
#pragma unroll
        for (int ks = 0; ks < 2; ks++) {
            uint32_t a[2][4];
#pragma unroll
            for (int mt = 0; mt < 2; mt++) {
                uint32_t addr = smem_u32(sA + (wr * 32 + mt * 16 + (lane & 15)) * SA_STRIDE
                                             + ks * 16 + (lane >> 4) * 8);
                ldsm_x4(a[mt][0], a[mt][1], a[mt][2], a[mt][3], addr);
            }
            uint32_t bf[4][4];
#pragma unroll
            for (int ng = 0; ng < 4; ng++) {
                uint32_t addr = smem_u32(sB + (ks * 16 + (lane & 15)) * SB_STRIDE
                                             + wc * 64 + ng * 16 + (lane >> 4) * 8);
                ldsm_x4_t(bf[ng][0], bf[ng][1], bf[ng][2], bf[ng][3], addr);
            }
#pragma unroll
            for (int mt = 0; mt < 2; mt++)
#pragma unroll
                for (int nt = 0; nt < 8; nt++)
                    mma16816(d[mt][nt], a[mt], bf[nt >> 1][(nt & 1) * 2],
                             bf[nt >> 1][(nt & 1) * 2 + 1]);
        }
    }

    // ---- epilogue: bias + relu + fp32 stores ----
#pragma unroll
    for (int mt = 0; mt < 2; mt++) {
        int corow = co0 + wr * 32 + mt * 16 + (lane >> 2);
#pragma unroll
        for (int h = 0; h < 2; h++) {
            int co = corow + h * 8;
            float bv = bias[co];
            float* orow = out + ((size_t)(b * 256 + co) * HW + y0) * HW;
#pragma unroll
            for (int nt = 0; nt < 8; nt++) {
                int px = wc * 64 + nt * 8 + (lane & 3) * 2;
                int yr = px >> 7, xx = px & 127;
                float2 v;
                v.x = fmaxf(d[mt][nt][h * 2 + 0] + bv, 0.f);
                v.y = fmaxf(d[mt][nt][h * 2 + 1] + bv, 0.f);
                *reinterpret_cast<float2*>(orow + yr * HW + xx) = v;
            }
        }
    }
}

// ---------------- launch ----------------
extern "C" void kernel_launch(void* const* d_in, const int* in_sizes, int n_in,
                              void* d_out, int out_size) {
    const float* x    = (const float*)d_in[0];
    const float* w1fr = (const float*)d_in[1];
    const float* w1fi = (const float*)d_in[2];
    const float* b1   = (const float*)d_in[3];
    const float* a1w1 = (const float*)d_in[4];
    const float* a1b1 = (const float*)d_in[5];
    const float* a1w2 = (const float*)d_in[6];
    const float* a1b2 = (const float*)d_in[7];
    const float* w2fr = (const float*)d_in[8];
    const float* w2fi = (const float*)d_in[9];
    const float* b2   = (const float*)d_in[10];
    const float* a2w1 = (const float*)d_in[11];
    const float* a2b1 = (const float*)d_in[12];
    const float* a2w2 = (const float*)d_in[13];
    const float* a2b2 = (const float*)d_in[14];
    float* out = (float*)d_out;

    float *yb, *bank1, *bank2, *gapb, *attnb;
    __half *wm1, *wm2;
    cudaGetSymbolAddress((void**)&yb,    g_y);
    cudaGetSymbolAddress((void**)&bank1, g_bank1);
    cudaGetSymbolAddress((void**)&bank2, g_bank2);
    cudaGetSymbolAddress((void**)&gapb,  g_gap);
    cudaGetSymbolAddress((void**)&attnb, g_attn);
    cudaGetSymbolAddress((void**)&wm1,   g_wmix1);
    cudaGetSymbolAddress((void**)&wm2,   g_wmix2);

    // kernel banks (independent of x)
    synth_kernel<<<(4 * CO * 128 + 255) / 256, 256>>>(w1fr, w1fi, bank1, 128);
    synth_kernel<<<(4 * CO * 256 + 255) / 256, 256>>>(w2fr, w2fi, bank2, 256);

    // layer 1
    gap_kernel<<<NB * 128, 256>>>(x, gapb);
    attn_kernel<<<NB, 64>>>(gapb, a1w1, a1b1, a1w2, a1b2, attnb, 128, 32);
    {
        int K = 128 * 9;
        int total = NB * CO * (K / 2);
        mix_kernel<<<(total + 255) / 256, 256>>>(bank1, attnb, wm1, K);
    }
    conv_hmma_kernel<128><<<dim3(64, 2, NB), 512>>>(x, wm1, b1, yb);

    // layer 2
    gap_kernel<<<NB * 256, 256>>>(yb, gapb);
    attn_kernel<<<NB, 64>>>(gapb, a2w1, a2b1, a2w2, a2b2, attnb, 256, 64);
    {
        int K = 256 * 9;
        int total = NB * CO * (K / 2);
        mix_kernel<<<(total + 255) / 256, 256>>>(bank2, attnb, wm2, K);
    }
    conv_hmma_kernel<256><<<dim3(64, 2, NB), 512>>>(yb, wm2, b2, out);
}

// round 7
// speedup vs baseline: 9.1724x; 1.3827x over previous
#include <cuda_runtime.h>
#include <cuda_fp16.h>
#include <math.h>
#include <stdint.h>

#define CO   256
#define HW   128
#define NB   16

// ---------------- device scratch ----------------
__device__ __align__(16) __half g_yh[(size_t)NB * CO * HW * HW];      // layer-1 out fp16
__device__ __align__(16) __half g_xh[(size_t)NB * 128 * HW * HW];     // x fp16
__device__ float  g_bank1[4 * 256 * 128 * 9];                          // [kb][co][tap][ci]
__device__ float  g_bank2[4 * 256 * 256 * 9];
__device__ __align__(16) __half g_wmix1[(size_t)NB * CO * 128 * 9];    // [b][co][tap*CIN+ci]
__device__ __align__(16) __half g_wmix2[(size_t)NB * CO * 256 * 9];
__device__ float  g_gap[NB * 256];
__device__ float  g_attn[NB * 4];

// ---------------- PTX helpers (base sm_103-safe only) ----------------
__device__ __forceinline__ uint32_t smem_u32(const void* p) {
    uint32_t a;
    asm("{ .reg .u64 t; cvta.to.shared.u64 t, %1; cvt.u32.u64 %0, t; }" : "=r"(a) : "l"(p));
    return a;
}
__device__ __forceinline__ void ldsm_x4(uint32_t& r0, uint32_t& r1, uint32_t& r2, uint32_t& r3,
                                        uint32_t addr) {
    asm volatile("ldmatrix.sync.aligned.m8n8.x4.shared.b16 {%0,%1,%2,%3}, [%4];"
                 : "=r"(r0), "=r"(r1), "=r"(r2), "=r"(r3) : "r"(addr));
}
__device__ __forceinline__ void ldsm_x4_t(uint32_t& r0, uint32_t& r1, uint32_t& r2, uint32_t& r3,
                                          uint32_t addr) {
    asm volatile("ldmatrix.sync.aligned.m8n8.x4.trans.shared.b16 {%0,%1,%2,%3}, [%4];"
                 : "=r"(r0), "=r"(r1), "=r"(r2), "=r"(r3) : "r"(addr));
}
__device__ __forceinline__ void mma16816(float* d, const uint32_t* a, uint32_t b0, uint32_t b1) {
    asm volatile("mma.sync.aligned.m16n8k16.row.col.f32.f16.f16.f32 "
                 "{%0,%1,%2,%3}, {%4,%5,%6,%7}, {%8,%9}, {%0,%1,%2,%3};"
                 : "+f"(d[0]), "+f"(d[1]), "+f"(d[2]), "+f"(d[3])
                 : "r"(a[0]), "r"(a[1]), "r"(a[2]), "r"(a[3]), "r"(b0), "r"(b1));
}
__device__ __forceinline__ void cp_async16(uint32_t dst, const void* src) {
    asm volatile("cp.async.ca.shared.global [%0], [%1], 16;" :: "r"(dst), "l"(src) : "memory");
}
#define CP_COMMIT()  asm volatile("cp.async.commit_group;" ::: "memory")
#define CP_WAIT(n)   asm volatile("cp.async.wait_group %0;" :: "n"(n) : "memory")

// ---------------- irfft2 synthesis into bank [kb][co][tap][ci] ----------------
__global__ void synth_kernel(const float* __restrict__ fr, const float* __restrict__ fi,
                             float* __restrict__ bank, int Ci) {
    int idx = blockIdx.x * blockDim.x + threadIdx.x;
    int total = 4 * CO * Ci;
    if (idx >= total) return;
    int ci = idx % Ci;
    int t  = idx / Ci;   // kb*CO + co

    const float* pr = fr + (size_t)idx * 6;
    const float* pi = fi + (size_t)idx * 6;
    float Fr[3][2], Fi[3][2];
#pragma unroll
    for (int a = 0; a < 3; a++)
#pragma unroll
        for (int x2 = 0; x2 < 2; x2++) {
            Fr[a][x2] = pr[a * 2 + x2];
            Fi[a][x2] = pi[a * 2 + x2];
        }
    const float Hs = 0.86602540378443864676f;
    const float cm[3] = { 1.f, -0.5f, -0.5f };
    const float sm[3] = { 0.f,  Hs,   -Hs  };

    float* outp = bank + ((size_t)t * 9) * Ci + ci;   // [t][tap][ci]
#pragma unroll
    for (int y = 0; y < 3; y++) {
        float Gr0 = 0.f, Gr1 = 0.f, Gi1 = 0.f;
#pragma unroll
        for (int ky = 0; ky < 3; ky++) {
            int m = (ky * y) % 3;
            float c = cm[m], s = sm[m];
            Gr0 += Fr[ky][0] * c - Fi[ky][0] * s;
            Gr1 += Fr[ky][1] * c - Fi[ky][1] * s;
            Gi1 += Fr[ky][1] * s + Fi[ky][1] * c;
        }
#pragma unroll
        for (int xx = 0; xx < 3; xx++)
            outp[(size_t)(y * 3 + xx) * Ci] = (Gr0 + 2.f * (Gr1 * cm[xx] - Gi1 * sm[xx])) * (1.f / 9.f);
    }
}

// ---------------- fp32 -> fp16 convert ----------------
__global__ void cvt_kernel(const float* __restrict__ x, __half* __restrict__ xh, int n4) {
    int i = blockIdx.x * blockDim.x + threadIdx.x;
    if (i >= n4) return;
    float4 v = reinterpret_cast<const float4*>(x)[i];
    __half2 h0 = __floats2half2_rn(v.x, v.y);
    __half2 h1 = __floats2half2_rn(v.z, v.w);
    uint2 u;
    u.x = *reinterpret_cast<uint32_t*>(&h0);
    u.y = *reinterpret_cast<uint32_t*>(&h1);
    reinterpret_cast<uint2*>(xh)[i] = u;
}

// ---------------- global average pool (fp32 in) ----------------
__global__ void gap_kernel(const float* __restrict__ in, float* __restrict__ gap) {
    const float4* p = reinterpret_cast<const float4*>(in + (size_t)blockIdx.x * (HW * HW));
    float s = 0.f;
    for (int i = threadIdx.x; i < HW * HW / 4; i += 256) {
        float4 v = p[i];
        s += (v.x + v.y) + (v.z + v.w);
    }
    __shared__ float red[8];
    for (int o = 16; o; o >>= 1) s += __shfl_down_sync(0xffffffffu, s, o);
    if ((threadIdx.x & 31) == 0) red[threadIdx.x >> 5] = s;
    __syncthreads();
    if (threadIdx.x < 8) {
        s = red[threadIdx.x];
        for (int o = 4; o; o >>= 1) s += __shfl_down_sync(0xffu, s, o);
        if (threadIdx.x == 0) gap[blockIdx.x] = s * (1.f / (HW * HW));
    }
}

// ---------------- global average pool (fp16 in) ----------------
__global__ void gap_h_kernel(const __half* __restrict__ in, float* __restrict__ gap) {
    const uint2* p = reinterpret_cast<const uint2*>(in + (size_t)blockIdx.x * (HW * HW));
    float s = 0.f;
    for (int i = threadIdx.x; i < HW * HW / 4; i += 256) {
        uint2 v = p[i];
        float2 a = __half22float2(*reinterpret_cast<__half2*>(&v.x));
        float2 c = __half22float2(*reinterpret_cast<__half2*>(&v.y));
        s += (a.x + a.y) + (c.x + c.y);
    }
    __shared__ float red[8];
    for (int o = 16; o; o >>= 1) s += __shfl_down_sync(0xffffffffu, s, o);
    if ((threadIdx.x & 31) == 0) red[threadIdx.x >> 5] = s;
    __syncthreads();
    if (threadIdx.x < 8) {
        s = red[threadIdx.x];
        for (int o = 4; o; o >>= 1) s += __shfl_down_sync(0xffu, s, o);
        if (threadIdx.x == 0) gap[blockIdx.x] = s * (1.f / (HW * HW));
    }
}

// ---------------- GAP -> MLP -> softmax ----------------
__global__ void attn_kernel(const float* __restrict__ gap, const float* __restrict__ w1,
                            const float* __restrict__ b1, const float* __restrict__ w2,
                            const float* __restrict__ b2, float* __restrict__ attn,
                            int C, int Hd) {
    __shared__ float gs[256];
    __shared__ float hbuf[64];
    int b = blockIdx.x;
    for (int i = threadIdx.x; i < C; i += blockDim.x) gs[i] = gap[b * C + i];
    __syncthreads();
    for (int j = threadIdx.x; j < Hd; j += blockDim.x) {
        float s = b1[j];
        for (int c = 0; c < C; c++) s += gs[c] * w1[c * Hd + j];
        hbuf[j] = fmaxf(s, 0.f);
    }
    __syncthreads();
    if (threadIdx.x == 0) {
        float l[4];
        float m = -1e30f;
        for (int k = 0; k < 4; k++) {
            float s = b2[k];
            for (int j = 0; j < Hd; j++) s += hbuf[j] * w2[j * 4 + k];
            l[k] = s; m = fmaxf(m, s);
        }
        float sum = 0.f;
        for (int k = 0; k < 4; k++) { l[k] = expf(l[k] - m); sum += l[k]; }
        float inv = 1.f / sum;
        for (int k = 0; k < 4; k++) attn[b * 4 + k] = l[k] * inv;
    }
}

// ---------------- weight mix ----------------
__global__ void mix_kernel(const float* __restrict__ bank, const float* __restrict__ attn,
                           __half* __restrict__ wmix, int K) {
    int total = NB * CO * (K / 2);
    int i = blockIdx.x * blockDim.x + threadIdx.x;
    if (i >= total) return;
    int perb = CO * (K / 2);
    int b = i / perb;
    int r = (i - b * perb) * 2;           // co*K + k  (tap-major k)
    float a0 = attn[b * 4 + 0], a1 = attn[b * 4 + 1];
    float a2 = attn[b * 4 + 2], a3 = attn[b * 4 + 3];
    int plane = CO * K;
    const float* p = bank + r;
    float x0 = a0 * p[0] + a1 * p[plane] + a2 * p[2 * plane] + a3 * p[3 * plane];
    float x1 = a0 * p[1] + a1 * p[plane + 1] + a2 * p[2 * plane + 1] + a3 * p[3 * plane + 1];
    reinterpret_cast<__half2*>(wmix)[i] = __floats2half2_rn(x0, x1);
}

// ---------------- HMMA implicit-GEMM conv ----------------
// CTA = (b, 128-co half, 2 rows = 256 px). K chunks of 64, tap-major.
// 16 warps 4x4: warp tile 32co x 64px. A via cp.async double-buffer; B reg-staged fp16.
#define SA 72                 // halves per A row (144B, conflict-free)
#define SB 264                // halves per B row (528B, conflict-free)
#define ABYTES (128 * SA * 2)
#define BBYTES (64 * SB * 2)
#define SMTOT  (2 * ABYTES + BBYTES)

template<int CIN, bool OUT_HALF>
__global__ void __launch_bounds__(512, 1)
conv_hmma_kernel(const __half* __restrict__ xh, const __half* __restrict__ wmix,
                 const float* __restrict__ bias, void* __restrict__ outv) {
    constexpr int K   = CIN * 9;
    constexpr int NCH = K / 64;
    constexpr int TPC = CIN / 64;       // chunks per tap

    extern __shared__ __align__(16) char smem[];
    const uint32_t sbase = smem_u32(smem);
    const uint32_t sb_u  = sbase + 2 * ABYTES;
    __half* sBp = reinterpret_cast<__half*>(smem + 2 * ABYTES);

    const int tid = threadIdx.x, wid = tid >> 5, lane = tid & 31;
    const int b   = blockIdx.z;
    const int co0 = blockIdx.y * 128;
    const int y0  = blockIdx.x * 2;
    const int wr = wid & 3, wc = wid >> 2;

    const __half* xb = xh + (size_t)b * CIN * HW * HW;
    const __half* wb = wmix + (size_t)(b * 256 + co0) * K;

    float d[2][8][4];
#pragma unroll
    for (int mt = 0; mt < 2; mt++)
#pragma unroll
        for (int nt = 0; nt < 8; nt++)
#pragma unroll
            for (int q = 0; q < 4; q++) d[mt][nt][q] = 0.f;

    // A cp.async mapping: thread -> rows (tid>>3, +64), seg tid&7 (8 halves)
    const int arow = tid >> 3, aseg = tid & 7;
    const __half* asrc0 = wb + (size_t)arow * K + aseg * 8;
    const uint32_t adst0 = sbase + (uint32_t)(arow * SA + aseg * 8) * 2;

    // B task mapping: 8 tasks/warp: kl = id>>1, yr = id&1
    const int bid0 = wid * 8;

    uint2 bS[8];

    // ---- prologue: A chunk 0 via cp.async, B chunk 0 into regs ----
    cp_async16(adst0, asrc0);
    cp_async16(adst0 + 64 * SA * 2, asrc0 + (size_t)64 * K);
    CP_COMMIT();
    {
        const int tap = 0, dy = 0, ci0 = 0;
#pragma unroll
        for (int t = 0; t < 8; t++) {
            int id = bid0 + t, kl = id >> 1, yr = id & 1;
            int gy = y0 + yr + dy - 1;
            uint2 v = make_uint2(0u, 0u);
            if ((unsigned)gy < 128u)
                v = __ldg(reinterpret_cast<const uint2*>(
                        xb + ((size_t)(ci0 + kl) * HW + gy) * HW) + lane);
            bS[t] = v;
        }
        (void)tap;
    }

    for (int c = 0; c < NCH; c++) {
        const int buf = c & 1;
        const int tap = c / TPC;
        const int dx  = tap % 3;

        __syncthreads();

        // ---- store B_c (apply dx shift) ----
#pragma unroll
        for (int t = 0; t < 8; t++) {
            int id = bid0 + t, kl = id >> 1, yr = id & 1;
            uint2 u = bS[t], o;
            if (dx == 1) {
                o = u;
            } else if (dx == 0) {
                uint32_t prev = __shfl_up_sync(0xffffffffu, u.y, 1);
                o.x = __byte_perm(prev, u.x, 0x5432);
                o.y = __byte_perm(u.x, u.y, 0x5432);
                if (lane == 0) o.x = u.x << 16;
            } else {
                uint32_t nxt = __shfl_down_sync(0xffffffffu, u.x, 1);
                o.x = __byte_perm(u.x, u.y, 0x5432);
                o.y = __byte_perm(u.y, nxt, 0x5432);
                if (lane == 31) o.y = u.y >> 16;
            }
            *reinterpret_cast<uint2*>(sBp + kl * SB + yr * 128 + lane * 4) = o;
        }

        // ---- prefetch chunk c+1 ----
        if (c + 1 < NCH) {
            const __half* asrc = asrc0 + (c + 1) * 64;
            const uint32_t adst = adst0 + (buf ^ 1) * ABYTES;
            cp_async16(adst, asrc);
            cp_async16(adst + 64 * SA * 2, asrc + (size_t)64 * K);
            CP_COMMIT();
            const int ntap = (c + 1) / TPC;
            const int ndy  = ntap / 3;
            const int nci0 = ((c + 1) % TPC) * 64;
#pragma unroll
            for (int t = 0; t < 8; t++) {
                int id = bid0 + t, kl = id >> 1, yr = id & 1;
                int gy = y0 + yr + ndy - 1;
                uint2 v = make_uint2(0u, 0u);
                if ((unsigned)gy < 128u)
                    v = __ldg(reinterpret_cast<const uint2*>(
                            xb + ((size_t)(nci0 + kl) * HW + gy) * HW) + lane);
                bS[t] = v;
            }
            CP_WAIT(1);
        } else {
            CP_WAIT(0);
        }

        __syncthreads();

        // ---- compute: 4 k16-steps ----
        const uint32_t sa = sbase + buf * ABYTES;
#pragma unroll
        for (int ks = 0; ks < 4; ks++) {
            uint32_t a[2][4];
#pragma unroll
            for (int mt = 0; mt < 2; mt++) {
                uint32_t addr = sa + (uint32_t)((wr * 32 + mt * 16 + (lane & 15)) * SA
                                                + ks * 16 + (lane >> 4) * 8) * 2;
                ldsm_x4(a[mt][0], a[mt][1], a[mt][2], a[mt][3], addr);
            }
            uint32_t bf[4][4];
#pragma unroll
            for (int ng = 0; ng < 4; ng++) {
                uint32_t addr = sb_u + (uint32_t)((ks * 16 + (lane & 15)) * SB
                                                  + wc * 64 + ng * 16 + (lane >> 4) * 8) * 2;
                ldsm_x4_t(bf[ng][0], bf[ng][1], bf[ng][2], bf[ng][3], addr);
            }
#pragma unroll
            for (int mt = 0; mt < 2; mt++)
#pragma unroll
                for (int nt = 0; nt < 8; nt++)
                    mma16816(d[mt][nt], a[mt], bf[nt >> 1][(nt & 1) * 2],
                             bf[nt >> 1][(nt & 1) * 2 + 1]);
        }
    }

    // ---- epilogue: bias + relu + stores ----
#pragma unroll
    for (int mt = 0; mt < 2; mt++) {
        int corow = co0 + wr * 32 + mt * 16 + (lane >> 2);
#pragma unroll
        for (int h = 0; h < 2; h++) {
            int co = corow + h * 8;
            float bv = bias[co];
            size_t base = ((size_t)(b * 256 + co) * HW + y0) * HW;
#pragma unroll
            for (int nt = 0; nt < 8; nt++) {
                int px = wc * 64 + nt * 8 + (lane & 3) * 2;
                int yr = px >> 7, xx = px & 127;
                float vx = fmaxf(d[mt][nt][h * 2 + 0] + bv, 0.f);
                float vy = fmaxf(d[mt][nt][h * 2 + 1] + bv, 0.f);
                if (OUT_HALF) {
                    __half2 hv = __floats2half2_rn(vx, vy);
                    *reinterpret_cast<__half2*>((__half*)outv + base + yr * HW + xx) = hv;
                } else {
                    float2 fv = make_float2(vx, vy);
                    *reinterpret_cast<float2*>((float*)outv + base + yr * HW + xx) = fv;
                }
            }
        }
    }
}

// ---------------- launch ----------------
extern "C" void kernel_launch(void* const* d_in, const int* in_sizes, int n_in,
                              void* d_out, int out_size) {
    const float* x    = (const float*)d_in[0];
    const float* w1fr = (const float*)d_in[1];
    const float* w1fi = (const float*)d_in[2];
    const float* b1   = (const float*)d_in[3];
    const float* a1w1 = (const float*)d_in[4];
    const float* a1b1 = (const float*)d_in[5];
    const float* a1w2 = (const float*)d_in[6];
    const float* a1b2 = (const float*)d_in[7];
    const float* w2fr = (const float*)d_in[8];
    const float* w2fi = (const float*)d_in[9];
    const float* b2   = (const float*)d_in[10];
    const float* a2w1 = (const float*)d_in[11];
    const float* a2b1 = (const float*)d_in[12];
    const float* a2w2 = (const float*)d_in[13];
    const float* a2b2 = (const float*)d_in[14];
    float* out = (float*)d_out;

    float *bank1, *bank2, *gapb, *attnb;
    __half *wm1, *wm2, *xhb, *yhb;
    cudaGetSymbolAddress((void**)&bank1, g_bank1);
    cudaGetSymbolAddress((void**)&bank2, g_bank2);
    cudaGetSymbolAddress((void**)&gapb,  g_gap);
    cudaGetSymbolAddress((void**)&attnb, g_attn);
    cudaGetSymbolAddress((void**)&wm1,   g_wmix1);
    cudaGetSymbolAddress((void**)&wm2,   g_wmix2);
    cudaGetSymbolAddress((void**)&xhb,   g_xh);
    cudaGetSymbolAddress((void**)&yhb,   g_yh);

    cudaFuncSetAttribute(conv_hmma_kernel<128, true>,
                         cudaFuncAttributeMaxDynamicSharedMemorySize, SMTOT);
    cudaFuncSetAttribute(conv_hmma_kernel<256, false>,
                         cudaFuncAttributeMaxDynamicSharedMemorySize, SMTOT);

    // kernel banks (independent of x) + x fp16 convert
    synth_kernel<<<(4 * CO * 128 + 255) / 256, 256>>>(w1fr, w1fi, bank1, 128);
    synth_kernel<<<(4 * CO * 256 + 255) / 256, 256>>>(w2fr, w2fi, bank2, 256);
    {
        int n4 = NB * 128 * HW * HW / 4;
        cvt_kernel<<<(n4 + 255) / 256, 256>>>(x, xhb, n4);
    }

    // layer 1
    gap_kernel<<<NB * 128, 256>>>(x, gapb);
    attn_kernel<<<NB, 64>>>(gapb, a1w1, a1b1, a1w2, a1b2, attnb, 128, 32);
    {
        int K = 128 * 9;
        int total = NB * CO * (K / 2);
        mix_kernel<<<(total + 255) / 256, 256>>>(bank1, attnb, wm1, K);
    }
    conv_hmma_kernel<128, true><<<dim3(64, 2, NB), 512, SMTOT>>>(xhb, wm1, b1, yhb);

    // layer 2
    gap_h_kernel<<<NB * 256, 256>>>(yhb, gapb);
    attn_kernel<<<NB, 64>>>(gapb, a2w1, a2b1, a2w2, a2b2, attnb, 256, 64);
    {
        int K = 256 * 9;
        int total = NB * CO * (K / 2);
        mix_kernel<<<(total + 255) / 256, 256>>>(bank2, attnb, wm2, K);
    }
    conv_hmma_kernel<256, false><<<dim3(64, 2, NB), 512, SMTOT>>>(yhb, wm2, b2, out);
}

// round 8
// speedup vs baseline: 9.9718x; 1.0871x over previous
#include <cuda_runtime.h>
#include <cuda_fp16.h>
#include <math.h>
#include <stdint.h>

#define CO   256
#define HW   128
#define NB   16

// ---------------- device scratch ----------------
__device__ __align__(16) __half g_yh[(size_t)NB * CO * HW * HW];      // layer-1 out fp16
__device__ __align__(16) __half g_xh[(size_t)NB * 128 * HW * HW];     // x fp16
__device__ float  g_bank1[4 * 256 * 128 * 9];                          // [kb][co][tap][ci]
__device__ float  g_bank2[4 * 256 * 256 * 9];
__device__ __align__(16) __half g_wmix1[(size_t)NB * CO * 128 * 9];    // [b][co][tap*CIN+ci]
__device__ __align__(16) __half g_wmix2[(size_t)NB * CO * 256 * 9];
__device__ float  g_gap1[NB * 128];
__device__ float  g_gap2[NB * 256];
__device__ float  g_attn[NB * 4];

// ---------------- PTX helpers (base sm_103-safe only) ----------------
__device__ __forceinline__ uint32_t smem_u32(const void* p) {
    uint32_t a;
    asm("{ .reg .u64 t; cvta.to.shared.u64 t, %1; cvt.u32.u64 %0, t; }" : "=r"(a) : "l"(p));
    return a;
}
__device__ __forceinline__ void ldsm_x4(uint32_t& r0, uint32_t& r1, uint32_t& r2, uint32_t& r3,
                                        uint32_t addr) {
    asm volatile("ldmatrix.sync.aligned.m8n8.x4.shared.b16 {%0,%1,%2,%3}, [%4];"
                 : "=r"(r0), "=r"(r1), "=r"(r2), "=r"(r3) : "r"(addr));
}
__device__ __forceinline__ void ldsm_x4_t(uint32_t& r0, uint32_t& r1, uint32_t& r2, uint32_t& r3,
                                          uint32_t addr) {
    asm volatile("ldmatrix.sync.aligned.m8n8.x4.trans.shared.b16 {%0,%1,%2,%3}, [%4];"
                 : "=r"(r0), "=r"(r1), "=r"(r2), "=r"(r3) : "r"(addr));
}
__device__ __forceinline__ void mma16816(float* d, const uint32_t* a, uint32_t b0, uint32_t b1) {
    asm volatile("mma.sync.aligned.m16n8k16.row.col.f32.f16.f16.f32 "
                 "{%0,%1,%2,%3}, {%4,%5,%6,%7}, {%8,%9}, {%0,%1,%2,%3};"
                 : "+f"(d[0]), "+f"(d[1]), "+f"(d[2]), "+f"(d[3])
                 : "r"(a[0]), "r"(a[1]), "r"(a[2]), "r"(a[3]), "r"(b0), "r"(b1));
}
__device__ __forceinline__ void cp_async16(uint32_t dst, const void* src) {
    asm volatile("cp.async.ca.shared.global [%0], [%1], 16;" :: "r"(dst), "l"(src) : "memory");
}
#define CP_COMMIT()  asm volatile("cp.async.commit_group;" ::: "memory")
#define CP_WAIT(n)   asm volatile("cp.async.wait_group %0;" :: "n"(n) : "memory")

// ---------------- irfft2 synthesis into bank [kb][co][tap][ci] ----------------
__global__ void synth_kernel(const float* __restrict__ fr, const float* __restrict__ fi,
                             float* __restrict__ bank, int Ci) {
    int idx = blockIdx.x * blockDim.x + threadIdx.x;
    int total = 4 * CO * Ci;
    if (idx >= total) return;
    int ci = idx % Ci;
    int t  = idx / Ci;   // kb*CO + co

    const float* pr = fr + (size_t)idx * 6;
    const float* pi = fi + (size_t)idx * 6;
    float Fr[3][2], Fi[3][2];
#pragma unroll
    for (int a = 0; a < 3; a++)
#pragma unroll
        for (int x2 = 0; x2 < 2; x2++) {
            Fr[a][x2] = pr[a * 2 + x2];
            Fi[a][x2] = pi[a * 2 + x2];
        }
    const float Hs = 0.86602540378443864676f;
    const float cm[3] = { 1.f, -0.5f, -0.5f };
    const float sm[3] = { 0.f,  Hs,   -Hs  };

    float* outp = bank + ((size_t)t * 9) * Ci + ci;   // [t][tap][ci]
#pragma unroll
    for (int y = 0; y < 3; y++) {
        float Gr0 = 0.f, Gr1 = 0.f, Gi1 = 0.f;
#pragma unroll
        for (int ky = 0; ky < 3; ky++) {
            int m = (ky * y) % 3;
            float c = cm[m], s = sm[m];
            Gr0 += Fr[ky][0] * c - Fi[ky][0] * s;
            Gr1 += Fr[ky][1] * c - Fi[ky][1] * s;
            Gi1 += Fr[ky][1] * s + Fi[ky][1] * c;
        }
#pragma unroll
        for (int xx = 0; xx < 3; xx++)
            outp[(size_t)(y * 3 + xx) * Ci] = (Gr0 + 2.f * (Gr1 * cm[xx] - Gi1 * sm[xx])) * (1.f / 9.f);
    }
}

// ---------------- fused fp32->fp16 convert + GAP (one pass over x) ----------------
__global__ void cvt_gap_kernel(const float* __restrict__ x, __half* __restrict__ xh,
                               float* __restrict__ gap) {
    const size_t base = (size_t)blockIdx.x * (HW * HW);
    const float4* p = reinterpret_cast<const float4*>(x + base);
    uint2* q = reinterpret_cast<uint2*>(xh + base);
    float s = 0.f;
    for (int i = threadIdx.x; i < HW * HW / 4; i += 256) {
        float4 v = p[i];
        s += (v.x + v.y) + (v.z + v.w);
        __half2 h0 = __floats2half2_rn(v.x, v.y);
        __half2 h1 = __floats2half2_rn(v.z, v.w);
        uint2 u;
        u.x = *reinterpret_cast<uint32_t*>(&h0);
        u.y = *reinterpret_cast<uint32_t*>(&h1);
        q[i] = u;
    }
    __shared__ float red[8];
    for (int o = 16; o; o >>= 1) s += __shfl_down_sync(0xffffffffu, s, o);
    if ((threadIdx.x & 31) == 0) red[threadIdx.x >> 5] = s;
    __syncthreads();
    if (threadIdx.x < 8) {
        s = red[threadIdx.x];
        for (int o = 4; o; o >>= 1) s += __shfl_down_sync(0xffu, s, o);
        if (threadIdx.x == 0) gap[blockIdx.x] = s * (1.f / (HW * HW));
    }
}

// ---------------- zero small buffer ----------------
__global__ void zero_kernel(float* __restrict__ p, int n) {
    int i = blockIdx.x * blockDim.x + threadIdx.x;
    if (i < n) p[i] = 0.f;
}

// ---------------- GAP -> MLP -> softmax ----------------
__global__ void attn_kernel(const float* __restrict__ gap, const float* __restrict__ w1,
                            const float* __restrict__ b1, const float* __restrict__ w2,
                            const float* __restrict__ b2, float* __restrict__ attn,
                            int C, int Hd) {
    __shared__ float gs[256];
    __shared__ float hbuf[64];
    int b = blockIdx.x;
    for (int i = threadIdx.x; i < C; i += blockDim.x) gs[i] = gap[b * C + i];
    __syncthreads();
    for (int j = threadIdx.x; j < Hd; j += blockDim.x) {
        float s = b1[j];
        for (int c = 0; c < C; c++) s += gs[c] * w1[c * Hd + j];
        hbuf[j] = fmaxf(s, 0.f);
    }
    __syncthreads();
    if (threadIdx.x == 0) {
        float l[4];
        float m = -1e30f;
        for (int k = 0; k < 4; k++) {
            float s = b2[k];
            for (int j = 0; j < Hd; j++) s += hbuf[j] * w2[j * 4 + k];
            l[k] = s; m = fmaxf(m, s);
        }
        float sum = 0.f;
        for (int k = 0; k < 4; k++) { l[k] = expf(l[k] - m); sum += l[k]; }
        float inv = 1.f / sum;
        for (int k = 0; k < 4; k++) attn[b * 4 + k] = l[k] * inv;
    }
}

// ---------------- weight mix ----------------
__global__ void mix_kernel(const float* __restrict__ bank, const float* __restrict__ attn,
                           __half* __restrict__ wmix, int K) {
    int total = NB * CO * (K / 2);
    int i = blockIdx.x * blockDim.x + threadIdx.x;
    if (i >= total) return;
    int perb = CO * (K / 2);
    int b = i / perb;
    int r = (i - b * perb) * 2;           // co*K + k  (tap-major k)
    float a0 = attn[b * 4 + 0], a1 = attn[b * 4 + 1];
    float a2 = attn[b * 4 + 2], a3 = attn[b * 4 + 3];
    int plane = CO * K;
    const float* p = bank + r;
    float x0 = a0 * p[0] + a1 * p[plane] + a2 * p[2 * plane] + a3 * p[3 * plane];
    float x1 = a0 * p[1] + a1 * p[plane + 1] + a2 * p[2 * plane + 1] + a3 * p[3 * plane + 1];
    reinterpret_cast<__half2*>(wmix)[i] = __floats2half2_rn(x0, x1);
}

// ---------------- HMMA implicit-GEMM conv (single-barrier pipeline) ----------------
// CTA = (b, 128-co half, 2 rows = 256 px). K chunks of 64, tap-major.
// A quad-buffered via cp.async; B triple-buffered, register-staged. One sync per chunk.
#define SA 72                 // halves per A row (144B, conflict-free)
#define SB 264                // halves per B row (528B, conflict-free)
#define ABYTES (128 * SA * 2)
#define BBYTES (64 * SB * 2)
#define SMTOT  (4 * ABYTES + 3 * BBYTES)

template<int CIN, bool OUT_HALF, bool GAP_OUT>
__global__ void __launch_bounds__(512, 1)
conv_hmma_kernel(const __half* __restrict__ xh, const __half* __restrict__ wmix,
                 const float* __restrict__ bias, void* __restrict__ outv,
                 float* __restrict__ gapout) {
    constexpr int K   = CIN * 9;
    constexpr int NCH = K / 64;
    constexpr int TPC = CIN / 64;       // chunks per tap

    extern __shared__ __align__(16) char smem[];
    const uint32_t sbase = smem_u32(smem);
    const uint32_t sbB   = sbase + 4 * ABYTES;
    __half* sBp = reinterpret_cast<__half*>(smem + 4 * ABYTES);

    const int tid = threadIdx.x, wid = tid >> 5, lane = tid & 31;
    const int b   = blockIdx.z;
    const int co0 = blockIdx.y * 128;
    const int y0  = blockIdx.x * 2;
    const int wr = wid & 3, wc = wid >> 2;

    const __half* xb = xh + (size_t)b * CIN * HW * HW;
    const __half* wb = wmix + (size_t)(b * 256 + co0) * K;

    float d[2][8][4];
#pragma unroll
    for (int mt = 0; mt < 2; mt++)
#pragma unroll
        for (int nt = 0; nt < 8; nt++)
#pragma unroll
            for (int q = 0; q < 4; q++) d[mt][nt][q] = 0.f;

    // A cp.async mapping: thread -> rows (tid>>3, +64), seg tid&7 (8 halves)
    const int arow = tid >> 3, aseg = tid & 7;
    const __half* asrc0 = wb + (size_t)arow * K + aseg * 8;
    const uint32_t adst0 = sbase + (uint32_t)(arow * SA + aseg * 8) * 2;

    // B task mapping: 8 tasks/warp: kl = id>>1, yr = id&1
    const int bid0 = wid * 8;

    uint2 bS[8];

    // LDG chunk cc of B into regs
    auto ldg_b = [&](int cc) {
        const int tap = cc / TPC;
        const int dy  = tap / 3;
        const int ci0 = (cc % TPC) * 64;
#pragma unroll
        for (int t = 0; t < 8; t++) {
            int id = bid0 + t, kl = id >> 1, yr = id & 1;
            int gy = y0 + yr + dy - 1;
            uint2 v = make_uint2(0u, 0u);
            if ((unsigned)gy < 128u)
                v = __ldg(reinterpret_cast<const uint2*>(
                        xb + ((size_t)(ci0 + kl) * HW + gy) * HW) + lane);
            bS[t] = v;
        }
    };
    // store staged regs (chunk cc) into B buffer cc%3, applying dx shift
    auto store_b = [&](int cc) {
        const int dx = (cc / TPC) % 3;
        __half* dst = sBp + (cc % 3) * (BBYTES / 2);
#pragma unroll
        for (int t = 0; t < 8; t++) {
            int id = bid0 + t, kl = id >> 1, yr = id & 1;
            uint2 u = bS[t], o;
            if (dx == 1) {
                o = u;
            } else if (dx == 0) {
                uint32_t prev = __shfl_up_sync(0xffffffffu, u.y, 1);
                o.x = __byte_perm(prev, u.x, 0x5432);
                o.y = __byte_perm(u.x, u.y, 0x5432);
                if (lane == 0) o.x = u.x << 16;
            } else {
                uint32_t nxt = __shfl_down_sync(0xffffffffu, u.x, 1);
                o.x = __byte_perm(u.x, u.y, 0x5432);
                o.y = __byte_perm(u.y, nxt, 0x5432);
                if (lane == 31) o.y = u.y >> 16;
            }
            *reinterpret_cast<uint2*>(dst + kl * SB + yr * 128 + lane * 4) = o;
        }
    };
    auto cpa_a = [&](int cc) {
        const __half* asrc = asrc0 + cc * 64;
        const uint32_t adst = adst0 + (cc & 3) * ABYTES;
        cp_async16(adst, asrc);
        cp_async16(adst + 64 * SA * 2, asrc + (size_t)64 * K);
    };

    // ---- prologue ----
    cpa_a(0); CP_COMMIT();
    cpa_a(1); CP_COMMIT();
    ldg_b(0);
    store_b(0);
    ldg_b(1);

    for (int c = 0; c < NCH; c++) {
        if (c + 1 < NCH) store_b(c + 1);
        if (c + 2 < NCH) { ldg_b(c + 2); cpa_a(c + 2); }
        CP_COMMIT();
        CP_WAIT(1);
        __syncthreads();

        // ---- compute chunk c: 4 k16-steps ----
        const uint32_t sa = sbase + (c & 3) * ABYTES;
        const uint32_t sb = sbB + (c % 3) * BBYTES;
#pragma unroll
        for (int ks = 0; ks < 4; ks++) {
            uint32_t a[2][4];
#pragma unroll
            for (int mt = 0; mt < 2; mt++) {
                uint32_t addr = sa + (uint32_t)((wr * 32 + mt * 16 + (lane & 15)) * SA
                                                + ks * 16 + (lane >> 4) * 8) * 2;
                ldsm_x4(a[mt][0], a[mt][1], a[mt][2], a[mt][3], addr);
            }
            uint32_t bf[4][4];
#pragma unroll
            for (int ng = 0; ng < 4; ng++) {
                uint32_t addr = sb + (uint32_t)((ks * 16 + (lane & 15)) * SB
                                                + wc * 64 + ng * 16 + (lane >> 4) * 8) * 2;
                ldsm_x4_t(bf[ng][0], bf[ng][1], bf[ng][2], bf[ng][3], addr);
            }
#pragma unroll
            for (int mt = 0; mt < 2; mt++)
#pragma unroll
                for (int nt = 0; nt < 8; nt++)
                    mma16816(d[mt][nt], a[mt], bf[nt >> 1][(nt & 1) * 2],
                             bf[nt >> 1][(nt & 1) * 2 + 1]);
        }
    }

    // ---- epilogue: bias + relu + stores (+ optional fused GAP of this layer's output) ----
#pragma unroll
    for (int mt = 0; mt < 2; mt++) {
        int corow = co0 + wr * 32 + mt * 16 + (lane >> 2);
#pragma unroll
        for (int h = 0; h < 2; h++) {
            int co = corow + h * 8;
            float bv = bias[co];
            size_t base = ((size_t)(b * 256 + co) * HW + y0) * HW;
            float gs = 0.f;
#pragma unroll
            for (int nt = 0; nt < 8; nt++) {
                int px = wc * 64 + nt * 8 + (lane & 3) * 2;
                int yr = px >> 7, xx = px & 127;
                float vx = fmaxf(d[mt][nt][h * 2 + 0] + bv, 0.f);
                float vy = fmaxf(d[mt][nt][h * 2 + 1] + bv, 0.f);
                if (GAP_OUT) gs += vx + vy;
                if (OUT_HALF) {
                    __half2 hv = __floats2half2_rn(vx, vy);
                    *reinterpret_cast<__half2*>((__half*)outv + base + yr * HW + xx) = hv;
                } else {
                    float2 fv = make_float2(vx, vy);
                    *reinterpret_cast<float2*>((float*)outv + base + yr * HW + xx) = fv;
                }
            }
            if (GAP_OUT) {
                gs += __shfl_xor_sync(0xffffffffu, gs, 1);
                gs += __shfl_xor_sync(0xffffffffu, gs, 2);
                if ((lane & 3) == 0)
                    atomicAdd(&gapout[b * 256 + co], gs * (1.f / (HW * HW)));
            }
        }
    }
}

// ---------------- launch ----------------
extern "C" void kernel_launch(void* const* d_in, const int* in_sizes, int n_in,
                              void* d_out, int out_size) {
    const float* x    = (const float*)d_in[0];
    const float* w1fr = (const float*)d_in[1];
    const float* w1fi = (const float*)d_in[2];
    const float* b1   = (const float*)d_in[3];
    const float* a1w1 = (const float*)d_in[4];
    const float* a1b1 = (const float*)d_in[5];
    const float* a1w2 = (const float*)d_in[6];
    const float* a1b2 = (const float*)d_in[7];
    const float* w2fr = (const float*)d_in[8];
    const float* w2fi = (const float*)d_in[9];
    const float* b2   = (const float*)d_in[10];
    const float* a2w1 = (const float*)d_in[11];
    const float* a2b1 = (const float*)d_in[12];
    const float* a2w2 = (const float*)d_in[13];
    const float* a2b2 = (const float*)d_in[14];
    float* out = (float*)d_out;

    float *bank1, *bank2, *gap1, *gap2, *attnb;
    __half *wm1, *wm2, *xhb, *yhb;
    cudaGetSymbolAddress((void**)&bank1, g_bank1);
    cudaGetSymbolAddress((void**)&bank2, g_bank2);
    cudaGetSymbolAddress((void**)&gap1,  g_gap1);
    cudaGetSymbolAddress((void**)&gap2,  g_gap2);
    cudaGetSymbolAddress((void**)&attnb, g_attn);
    cudaGetSymbolAddress((void**)&wm1,   g_wmix1);
    cudaGetSymbolAddress((void**)&wm2,   g_wmix2);
    cudaGetSymbolAddress((void**)&xhb,   g_xh);
    cudaGetSymbolAddress((void**)&yhb,   g_yh);

    cudaFuncSetAttribute(conv_hmma_kernel<128, true, true>,
                         cudaFuncAttributeMaxDynamicSharedMemorySize, SMTOT);
    cudaFuncSetAttribute(conv_hmma_kernel<256, false, false>,
                         cudaFuncAttributeMaxDynamicSharedMemorySize, SMTOT);

    // kernel banks (independent of x); zero gap2 accumulator
    synth_kernel<<<(4 * CO * 128 + 255) / 256, 256>>>(w1fr, w1fi, bank1, 128);
    synth_kernel<<<(4 * CO * 256 + 255) / 256, 256>>>(w2fr, w2fi, bank2, 256);
    zero_kernel<<<(NB * 256 + 255) / 256, 256>>>(gap2, NB * 256);

    // layer 1 (cvt + gap fused; conv1 epilogue produces gap2 for layer 2)
    cvt_gap_kernel<<<NB * 128, 256>>>(x, xhb, gap1);
    attn_kernel<<<NB, 64>>>(gap1, a1w1, a1b1, a1w2, a1b2, attnb, 128, 32);
    {
        int K = 128 * 9;
        int total = NB * CO * (K / 2);
        mix_kernel<<<(total + 255) / 256, 256>>>(bank1, attnb, wm1, K);
    }
    conv_hmma_kernel<128, true, true><<<dim3(64, 2, NB), 512, SMTOT>>>(xhb, wm1, b1, yhb, gap2);

    // layer 2
    attn_kernel<<<NB, 64>>>(gap2, a2w1, a2b1, a2w2, a2b2, attnb, 256, 64);
    {
        int K = 256 * 9;
        int total = NB * CO * (K / 2);
        mix_kernel<<<(total + 255) / 256, 256>>>(bank2, attnb, wm2, K);
    }
    conv_hmma_kernel<256, false, false><<<dim3(64, 2, NB), 512, SMTOT>>>(yhb, wm2, b2, out, nullptr);
}

// round 9
// speedup vs baseline: 10.0284x; 1.0057x over previous
#include <cuda_runtime.h>
#include <cuda_fp16.h>
#include <math.h>
#include <stdint.h>

#define CO   256
#define HW   128
#define NB   16

// ---------------- device scratch ----------------
__device__ __align__(16) __half g_yh[(size_t)NB * CO * HW * HW];      // layer-1 out fp16
__device__ __align__(16) __half g_xh[(size_t)NB * 128 * HW * HW];     // x fp16
__device__ float  g_bank1[4 * 256 * 128 * 9];                          // [kb][co][tap][ci]
__device__ float  g_bank2[4 * 256 * 256 * 9];
__device__ __align__(16) __half g_wmix1[(size_t)NB * CO * 128 * 9];    // [b][co][tap*CIN+ci]
__device__ __align__(16) __half g_wmix2[(size_t)NB * CO * 256 * 9];
__device__ float  g_gap1[NB * 128];
__device__ float  g_gap2[NB * 256];
__device__ float  g_attn[NB * 4];

// ---------------- PTX helpers (base sm_103-safe only) ----------------
__device__ __forceinline__ uint32_t smem_u32(const void* p) {
    uint32_t a;
    asm("{ .reg .u64 t; cvta.to.shared.u64 t, %1; cvt.u32.u64 %0, t; }" : "=r"(a) : "l"(p));
    return a;
}
__device__ __forceinline__ void ldsm_x4(uint32_t& r0, uint32_t& r1, uint32_t& r2, uint32_t& r3,
                                        uint32_t addr) {
    asm volatile("ldmatrix.sync.aligned.m8n8.x4.shared.b16 {%0,%1,%2,%3}, [%4];"
                 : "=r"(r0), "=r"(r1), "=r"(r2), "=r"(r3) : "r"(addr));
}
__device__ __forceinline__ void ldsm_x4_t(uint32_t& r0, uint32_t& r1, uint32_t& r2, uint32_t& r3,
                                          uint32_t addr) {
    asm volatile("ldmatrix.sync.aligned.m8n8.x4.trans.shared.b16 {%0,%1,%2,%3}, [%4];"
                 : "=r"(r0), "=r"(r1), "=r"(r2), "=r"(r3) : "r"(addr));
}
__device__ __forceinline__ void mma16816(float* d, const uint32_t* a, uint32_t b0, uint32_t b1) {
    asm volatile("mma.sync.aligned.m16n8k16.row.col.f32.f16.f16.f32 "
                 "{%0,%1,%2,%3}, {%4,%5,%6,%7}, {%8,%9}, {%0,%1,%2,%3};"
                 : "+f"(d[0]), "+f"(d[1]), "+f"(d[2]), "+f"(d[3])
                 : "r"(a[0]), "r"(a[1]), "r"(a[2]), "r"(a[3]), "r"(b0), "r"(b1));
}
__device__ __forceinline__ void cp_async16(uint32_t dst, const void* src) {
    asm volatile("cp.async.ca.shared.global [%0], [%1], 16;" :: "r"(dst), "l"(src) : "memory");
}
#define CP_COMMIT()  asm volatile("cp.async.commit_group;" ::: "memory")
#define CP_WAIT(n)   asm volatile("cp.async.wait_group %0;" :: "n"(n) : "memory")

// ---------------- irfft2 synthesis into bank [kb][co][tap][ci] ----------------
__global__ void synth_kernel(const float* __restrict__ fr, const float* __restrict__ fi,
                             float* __restrict__ bank, int Ci) {
    int idx = blockIdx.x * blockDim.x + threadIdx.x;
    int total = 4 * CO * Ci;
    if (idx >= total) return;
    int ci = idx % Ci;
    int t  = idx / Ci;   // kb*CO + co

    const float* pr = fr + (size_t)idx * 6;
    const float* pi = fi + (size_t)idx * 6;
    float Fr[3][2], Fi[3][2];
#pragma unroll
    for (int a = 0; a < 3; a++)
#pragma unroll
        for (int x2 = 0; x2 < 2; x2++) {
            Fr[a][x2] = pr[a * 2 + x2];
            Fi[a][x2] = pi[a * 2 + x2];
        }
    const float Hs = 0.86602540378443864676f;
    const float cm[3] = { 1.f, -0.5f, -0.5f };
    const float sm[3] = { 0.f,  Hs,   -Hs  };

    float* outp = bank + ((size_t)t * 9) * Ci + ci;   // [t][tap][ci]
#pragma unroll
    for (int y = 0; y < 3; y++) {
        float Gr0 = 0.f, Gr1 = 0.f, Gi1 = 0.f;
#pragma unroll
        for (int ky = 0; ky < 3; ky++) {
            int m = (ky * y) % 3;
            float c = cm[m], s = sm[m];
            Gr0 += Fr[ky][0] * c - Fi[ky][0] * s;
            Gr1 += Fr[ky][1] * c - Fi[ky][1] * s;
            Gi1 += Fr[ky][1] * s + Fi[ky][1] * c;
        }
#pragma unroll
        for (int xx = 0; xx < 3; xx++)
            outp[(size_t)(y * 3 + xx) * Ci] = (Gr0 + 2.f * (Gr1 * cm[xx] - Gi1 * sm[xx])) * (1.f / 9.f);
    }
}

// ---------------- fused fp32->fp16 convert + GAP (one pass over x) ----------------
__global__ void cvt_gap_kernel(const float* __restrict__ x, __half* __restrict__ xh,
                               float* __restrict__ gap) {
    const size_t base = (size_t)blockIdx.x * (HW * HW);
    const float4* p = reinterpret_cast<const float4*>(x + base);
    uint2* q = reinterpret_cast<uint2*>(xh + base);
    float s = 0.f;
    for (int i = threadIdx.x; i < HW * HW / 4; i += 256) {
        float4 v = p[i];
        s += (v.x + v.y) + (v.z + v.w);
        __half2 h0 = __floats2half2_rn(v.x, v.y);
        __half2 h1 = __floats2half2_rn(v.z, v.w);
        uint2 u;
        u.x = *reinterpret_cast<uint32_t*>(&h0);
        u.y = *reinterpret_cast<uint32_t*>(&h1);
        q[i] = u;
    }
    __shared__ float red[8];
    for (int o = 16; o; o >>= 1) s += __shfl_down_sync(0xffffffffu, s, o);
    if ((threadIdx.x & 31) == 0) red[threadIdx.x >> 5] = s;
    __syncthreads();
    if (threadIdx.x < 8) {
        s = red[threadIdx.x];
        for (int o = 4; o; o >>= 1) s += __shfl_down_sync(0xffu, s, o);
        if (threadIdx.x == 0) gap[blockIdx.x] = s * (1.f / (HW * HW));
    }
}

// ---------------- zero small buffer ----------------
__global__ void zero_kernel(float* __restrict__ p, int n) {
    int i = blockIdx.x * blockDim.x + threadIdx.x;
    if (i < n) p[i] = 0.f;
}

// ---------------- GAP -> MLP -> softmax ----------------
__global__ void attn_kernel(const float* __restrict__ gap, const float* __restrict__ w1,
                            const float* __restrict__ b1, const float* __restrict__ w2,
                            const float* __restrict__ b2, float* __restrict__ attn,
                            int C, int Hd) {
    __shared__ float gs[256];
    __shared__ float hbuf[64];
    int b = blockIdx.x;
    for (int i = threadIdx.x; i < C; i += blockDim.x) gs[i] = gap[b * C + i];
    __syncthreads();
    for (int j = threadIdx.x; j < Hd; j += blockDim.x) {
        float s = b1[j];
        for (int c = 0; c < C; c++) s += gs[c] * w1[c * Hd + j];
        hbuf[j] = fmaxf(s, 0.f);
    }
    __syncthreads();
    if (threadIdx.x == 0) {
        float l[4];
        float m = -1e30f;
        for (int k = 0; k < 4; k++) {
            float s = b2[k];
            for (int j = 0; j < Hd; j++) s += hbuf[j] * w2[j * 4 + k];
            l[k] = s; m = fmaxf(m, s);
        }
        float sum = 0.f;
        for (int k = 0; k < 4; k++) { l[k] = expf(l[k] - m); sum += l[k]; }
        float inv = 1.f / sum;
        for (int k = 0; k < 4; k++) attn[b * 4 + k] = l[k] * inv;
    }
}

// ---------------- weight mix ----------------
__global__ void mix_kernel(const float* __restrict__ bank, const float* __restrict__ attn,
                           __half* __restrict__ wmix, int K) {
    int total = NB * CO * (K / 2);
    int i = blockIdx.x * blockDim.x + threadIdx.x;
    if (i >= total) return;
    int perb = CO * (K / 2);
    int b = i / perb;
    int r = (i - b * perb) * 2;           // co*K + k  (tap-major k)
    float a0 = attn[b * 4 + 0], a1 = attn[b * 4 + 1];
    float a2 = attn[b * 4 + 2], a3 = attn[b * 4 + 3];
    int plane = CO * K;
    const float* p = bank + r;
    float x0 = a0 * p[0] + a1 * p[plane] + a2 * p[2 * plane] + a3 * p[3 * plane];
    float x1 = a0 * p[1] + a1 * p[plane + 1] + a2 * p[2 * plane + 1] + a3 * p[3 * plane + 1];
    reinterpret_cast<__half2*>(wmix)[i] = __floats2half2_rn(x0, x1);
}

// ---------------- HMMA implicit-GEMM conv (produce interleaved into compute) ----------------
// CTA = (b, 128-co half, 2 rows = 256 px). K chunks of 64, tap-major.
// A quad-buffered via cp.async; B triple-buffered, register-staged. One sync per chunk,
// with the produce phase (B store, LDG, cp.async) interleaved between the 4 k-steps.
#define SA 72                 // halves per A row (144B, conflict-free)
#define SB 264                // halves per B row (528B, conflict-free)
#define ABYTES (128 * SA * 2)
#define BBYTES (64 * SB * 2)
#define SMTOT  (4 * ABYTES + 3 * BBYTES)

template<int CIN, bool OUT_HALF, bool GAP_OUT>
__global__ void __launch_bounds__(512, 1)
conv_hmma_kernel(const __half* __restrict__ xh, const __half* __restrict__ wmix,
                 const float* __restrict__ bias, void* __restrict__ outv,
                 float* __restrict__ gapout) {
    constexpr int K   = CIN * 9;
    constexpr int NCH = K / 64;
    constexpr int TPC = CIN / 64;       // chunks per tap

    extern __shared__ __align__(16) char smem[];
    const uint32_t sbase = smem_u32(smem);
    const uint32_t sbB   = sbase + 4 * ABYTES;
    __half* sBp = reinterpret_cast<__half*>(smem + 4 * ABYTES);

    const int tid = threadIdx.x, wid = tid >> 5, lane = tid & 31;
    const int b   = blockIdx.z;
    const int co0 = blockIdx.y * 128;
    const int y0  = blockIdx.x * 2;
    const int wr = wid & 3, wc = wid >> 2;

    const __half* xb = xh + (size_t)b * CIN * HW * HW;
    const __half* wb = wmix + (size_t)(b * 256 + co0) * K;

    float d[2][8][4];
#pragma unroll
    for (int mt = 0; mt < 2; mt++)
#pragma unroll
        for (int nt = 0; nt < 8; nt++)
#pragma unroll
            for (int q = 0; q < 4; q++) d[mt][nt][q] = 0.f;

    // A cp.async mapping: thread -> rows (tid>>3, +64), seg tid&7 (8 halves)
    const int arow = tid >> 3, aseg = tid & 7;
    const __half* asrc0 = wb + (size_t)arow * K + aseg * 8;
    const uint32_t adst0 = sbase + (uint32_t)(arow * SA + aseg * 8) * 2;

    // B task mapping: 8 tasks/warp: kl = id>>1, yr = id&1
    const int bid0 = wid * 8;

    uint2 bS[8];

    // LDG chunk cc of B into regs
    auto ldg_b = [&](int cc) {
        const int tap = cc / TPC;
        const int dy  = tap / 3;
        const int ci0 = (cc % TPC) * 64;
#pragma unroll
        for (int t = 0; t < 8; t++) {
            int id = bid0 + t, kl = id >> 1, yr = id & 1;
            int gy = y0 + yr + dy - 1;
            uint2 v = make_uint2(0u, 0u);
            if ((unsigned)gy < 128u)
                v = __ldg(reinterpret_cast<const uint2*>(
                        xb + ((size_t)(ci0 + kl) * HW + gy) * HW) + lane);
            bS[t] = v;
        }
    };
    // store staged regs (chunk cc) into B buffer cc%3, applying dx shift
    auto store_b = [&](int cc) {
        const int dx = (cc / TPC) % 3;
        __half* dst = sBp + (cc % 3) * (BBYTES / 2);
#pragma unroll
        for (int t = 0; t < 8; t++) {
            int id = bid0 + t, kl = id >> 1, yr = id & 1;
            uint2 u = bS[t], o;
            if (dx == 1) {
                o = u;
            } else if (dx == 0) {
                uint32_t prev = __shfl_up_sync(0xffffffffu, u.y, 1);
                o.x = __byte_perm(prev, u.x, 0x5432);
                o.y = __byte_perm(u.x, u.y, 0x5432);
                if (lane == 0) o.x = u.x << 16;
            } else {
                uint32_t nxt = __shfl_down_sync(0xffffffffu, u.x, 1);
                o.x = __byte_perm(u.x, u.y, 0x5432);
                o.y = __byte_perm(u.y, nxt, 0x5432);
                if (lane == 31) o.y = u.y >> 16;
            }
            *reinterpret_cast<uint2*>(dst + kl * SB + yr * 128 + lane * 4) = o;
        }
    };
    auto cpa_a = [&](int cc) {
        const __half* asrc = asrc0 + cc * 64;
        const uint32_t adst = adst0 + (cc & 3) * ABYTES;
        cp_async16(adst, asrc);
        cp_async16(adst + 64 * SA * 2, asrc + (size_t)64 * K);
    };

    // one k16-step of chunk c
    auto kstep = [&](int c, int ks) {
        const uint32_t sa = sbase + (c & 3) * ABYTES;
        const uint32_t sb = sbB + (c % 3) * BBYTES;
        uint32_t a[2][4];
#pragma unroll
        for (int mt = 0; mt < 2; mt++) {
            uint32_t addr = sa + (uint32_t)((wr * 32 + mt * 16 + (lane & 15)) * SA
                                            + ks * 16 + (lane >> 4) * 8) * 2;
            ldsm_x4(a[mt][0], a[mt][1], a[mt][2], a[mt][3], addr);
        }
        uint32_t bf[4][4];
#pragma unroll
        for (int ng = 0; ng < 4; ng++) {
            uint32_t addr = sb + (uint32_t)((ks * 16 + (lane & 15)) * SB
                                            + wc * 64 + ng * 16 + (lane >> 4) * 8) * 2;
            ldsm_x4_t(bf[ng][0], bf[ng][1], bf[ng][2], bf[ng][3], addr);
        }
#pragma unroll
        for (int mt = 0; mt < 2; mt++)
#pragma unroll
            for (int nt = 0; nt < 8; nt++)
                mma16816(d[mt][nt], a[mt], bf[nt >> 1][(nt & 1) * 2],
                         bf[nt >> 1][(nt & 1) * 2 + 1]);
    };

    // ---- prologue ----
    cpa_a(0); CP_COMMIT();
    cpa_a(1); CP_COMMIT();
    ldg_b(0);
    store_b(0);
    ldg_b(1);
    CP_WAIT(1);
    __syncthreads();

    for (int c = 0; c < NCH; c++) {
        // produce interleaved between k-steps; one barrier at iteration end
        kstep(c, 0);
        if (c + 1 < NCH) store_b(c + 1);       // writes buf (c+1)%3, readers on c%3
        kstep(c, 1);
        if (c + 2 < NCH) ldg_b(c + 2);         // after store_b consumed bS (WAR in order)
        kstep(c, 2);
        if (c + 2 < NCH) cpa_a(c + 2);
        CP_COMMIT();
        kstep(c, 3);
        CP_WAIT(1);                            // A(c+1) landed
        __syncthreads();                       // B(c+1) stores visible; buf c%3 free
    }

    // ---- epilogue: bias + relu + stores (+ optional fused GAP of this layer's output) ----
#pragma unroll
    for (int mt = 0; mt < 2; mt++) {
        int corow = co0 + wr * 32 + mt * 16 + (lane >> 2);
#pragma unroll
        for (int h = 0; h < 2; h++) {
            int co = corow + h * 8;
            float bv = bias[co];
            size_t base = ((size_t)(b * 256 + co) * HW + y0) * HW;
            float gs = 0.f;
#pragma unroll
            for (int nt = 0; nt < 8; nt++) {
                int px = wc * 64 + nt * 8 + (lane & 3) * 2;
                int yr = px >> 7, xx = px & 127;
                float vx = fmaxf(d[mt][nt][h * 2 + 0] + bv, 0.f);
                float vy = fmaxf(d[mt][nt][h * 2 + 1] + bv, 0.f);
                if (GAP_OUT) gs += vx + vy;
                if (OUT_HALF) {
                    __half2 hv = __floats2half2_rn(vx, vy);
                    *reinterpret_cast<__half2*>((__half*)outv + base + yr * HW + xx) = hv;
                } else {
                    float2 fv = make_float2(vx, vy);
                    *reinterpret_cast<float2*>((float*)outv + base + yr * HW + xx) = fv;
                }
            }
            if (GAP_OUT) {
                gs += __shfl_xor_sync(0xffffffffu, gs, 1);
                gs += __shfl_xor_sync(0xffffffffu, gs, 2);
                if ((lane & 3) == 0)
                    atomicAdd(&gapout[b * 256 + co], gs * (1.f / (HW * HW)));
            }
        }
    }
}

// ---------------- launch ----------------
extern "C" void kernel_launch(void* const* d_in, const int* in_sizes, int n_in,
                              void* d_out, int out_size) {
    const float* x    = (const float*)d_in[0];
    const float* w1fr = (const float*)d_in[1];
    const float* w1fi = (const float*)d_in[2];
    const float* b1   = (const float*)d_in[3];
    const float* a1w1 = (const float*)d_in[4];
    const float* a1b1 = (const float*)d_in[5];
    const float* a1w2 = (const float*)d_in[6];
    const float* a1b2 = (const float*)d_in[7];
    const float* w2fr = (const float*)d_in[8];
    const float* w2fi = (const float*)d_in[9];
    const float* b2   = (const float*)d_in[10];
    const float* a2w1 = (const float*)d_in[11];
    const float* a2b1 = (const float*)d_in[12];
    const float* a2w2 = (const float*)d_in[13];
    const float* a2b2 = (const float*)d_in[14];
    float* out = (float*)d_out;

    float *bank1, *bank2, *gap1, *gap2, *attnb;
    __half *wm1, *wm2, *xhb, *yhb;
    cudaGetSymbolAddress((void**)&bank1, g_bank1);
    cudaGetSymbolAddress((void**)&bank2, g_bank2);
    cudaGetSymbolAddress((void**)&gap1,  g_gap1);
    cudaGetSymbolAddress((void**)&gap2,  g_gap2);
    cudaGetSymbolAddress((void**)&attnb, g_attn);
    cudaGetSymbolAddress((void**)&wm1,   g_wmix1);
    cudaGetSymbolAddress((void**)&wm2,   g_wmix2);
    cudaGetSymbolAddress((void**)&xhb,   g_xh);
    cudaGetSymbolAddress((void**)&yhb,   g_yh);

    cudaFuncSetAttribute(conv_hmma_kernel<128, true, true>,
                         cudaFuncAttributeMaxDynamicSharedMemorySize, SMTOT);
    cudaFuncSetAttribute(conv_hmma_kernel<256, false, false>,
                         cudaFuncAttributeMaxDynamicSharedMemorySize, SMTOT);

    // Launch order chosen so conv1 is launch #5 (ncu captures -s 5 -c 1).
    // layer 1
    synth_kernel<<<(4 * CO * 128 + 255) / 256, 256>>>(w1fr, w1fi, bank1, 128);      // 0
    cvt_gap_kernel<<<NB * 128, 256>>>(x, xhb, gap1);                                 // 1
    attn_kernel<<<NB, 64>>>(gap1, a1w1, a1b1, a1w2, a1b2, attnb, 128, 32);           // 2
    {
        int K = 128 * 9;
        int total = NB * CO * (K / 2);
        mix_kernel<<<(total + 255) / 256, 256>>>(bank1, attnb, wm1, K);              // 3
    }
    zero_kernel<<<(NB * 256 + 255) / 256, 256>>>(gap2, NB * 256);                    // 4
    conv_hmma_kernel<128, true, true><<<dim3(64, 2, NB), 512, SMTOT>>>(xhb, wm1, b1, yhb, gap2);  // 5

    // layer 2
    synth_kernel<<<(4 * CO * 256 + 255) / 256, 256>>>(w2fr, w2fi, bank2, 256);       // 6
    attn_kernel<<<NB, 64>>>(gap2, a2w1, a2b1, a2w2, a2b2, attnb, 256, 64);           // 7
    {
        int K = 256 * 9;
        int total = NB * CO * (K / 2);
        mix_kernel<<<(total + 255) / 256, 256>>>(bank2, attnb, wm2, K);              // 8
    }
    conv_hmma_kernel<256, false, false><<<dim3(64, 2, NB), 512, SMTOT>>>(yhb, wm2, b2, out, nullptr);  // 9
}

// round 10
// speedup vs baseline: 10.2370x; 1.0208x over previous
#include <cuda_runtime.h>
#include <cuda_fp16.h>
#include <math.h>
#include <stdint.h>

#define CO   256
#define HW   128
#define NB   16

// ---------------- device scratch ----------------
__device__ __align__(16) __half g_yh[(size_t)NB * CO * HW * HW];      // layer-1 out fp16
__device__ __align__(16) __half g_xh[(size_t)NB * 128 * HW * HW];     // x fp16
__device__ float  g_bank1[4 * 256 * 128 * 9];                          // [kb][co][tap][ci]
__device__ float  g_bank2[4 * 256 * 256 * 9];
__device__ __align__(16) __half g_wmix1[(size_t)NB * CO * 128 * 9];    // [b][co][tap*CIN+ci]
__device__ __align__(16) __half g_wmix2[(size_t)NB * CO * 256 * 9];
__device__ float  g_gap1[NB * 128];
__device__ float  g_gap2[NB * 256];
__device__ float  g_attn[NB * 4];

// ---------------- PTX helpers (base sm_103-safe only) ----------------
__device__ __forceinline__ uint32_t smem_u32(const void* p) {
    uint32_t a;
    asm("{ .reg .u64 t; cvta.to.shared.u64 t, %1; cvt.u32.u64 %0, t; }" : "=r"(a) : "l"(p));
    return a;
}
__device__ __forceinline__ void ldsm_x4(uint32_t& r0, uint32_t& r1, uint32_t& r2, uint32_t& r3,
                                        uint32_t addr) {
    asm volatile("ldmatrix.sync.aligned.m8n8.x4.shared.b16 {%0,%1,%2,%3}, [%4];"
                 : "=r"(r0), "=r"(r1), "=r"(r2), "=r"(r3) : "r"(addr));
}
__device__ __forceinline__ void ldsm_x4_t(uint32_t& r0, uint32_t& r1, uint32_t& r2, uint32_t& r3,
                                          uint32_t addr) {
    asm volatile("ldmatrix.sync.aligned.m8n8.x4.trans.shared.b16 {%0,%1,%2,%3}, [%4];"
                 : "=r"(r0), "=r"(r1), "=r"(r2), "=r"(r3) : "r"(addr));
}
__device__ __forceinline__ void mma16816(float* d, const uint32_t* a, uint32_t b0, uint32_t b1) {
    asm volatile("mma.sync.aligned.m16n8k16.row.col.f32.f16.f16.f32 "
                 "{%0,%1,%2,%3}, {%4,%5,%6,%7}, {%8,%9}, {%0,%1,%2,%3};"
                 : "+f"(d[0]), "+f"(d[1]), "+f"(d[2]), "+f"(d[3])
                 : "r"(a[0]), "r"(a[1]), "r"(a[2]), "r"(a[3]), "r"(b0), "r"(b1));
}
__device__ __forceinline__ void cp_async16(uint32_t dst, const void* src) {
    asm volatile("cp.async.ca.shared.global [%0], [%1], 16;" :: "r"(dst), "l"(src) : "memory");
}
#define CP_COMMIT()  asm volatile("cp.async.commit_group;" ::: "memory")
#define CP_WAIT(n)   asm volatile("cp.async.wait_group %0;" :: "n"(n) : "memory")

// ---------------- irfft2 synthesis (device body) ----------------
__device__ __forceinline__ void synth_body(const float* __restrict__ fr,
                                           const float* __restrict__ fi,
                                           float* __restrict__ bank, int Ci, int idx) {
    int ci = idx % Ci;
    int t  = idx / Ci;   // kb*CO + co

    const float* pr = fr + (size_t)idx * 6;
    const float* pi = fi + (size_t)idx * 6;
    float Fr[3][2], Fi[3][2];
#pragma unroll
    for (int a = 0; a < 3; a++)
#pragma unroll
        for (int x2 = 0; x2 < 2; x2++) {
            Fr[a][x2] = pr[a * 2 + x2];
            Fi[a][x2] = pi[a * 2 + x2];
        }
    const float Hs = 0.86602540378443864676f;
    const float cm[3] = { 1.f, -0.5f, -0.5f };
    const float sm[3] = { 0.f,  Hs,   -Hs  };

    float* outp = bank + ((size_t)t * 9) * Ci + ci;   // [t][tap][ci]
#pragma unroll
    for (int y = 0; y < 3; y++) {
        float Gr0 = 0.f, Gr1 = 0.f, Gi1 = 0.f;
#pragma unroll
        for (int ky = 0; ky < 3; ky++) {
            int m = (ky * y) % 3;
            float c = cm[m], s = sm[m];
            Gr0 += Fr[ky][0] * c - Fi[ky][0] * s;
            Gr1 += Fr[ky][1] * c - Fi[ky][1] * s;
            Gi1 += Fr[ky][1] * s + Fi[ky][1] * c;
        }
#pragma unroll
        for (int xx = 0; xx < 3; xx++)
            outp[(size_t)(y * 3 + xx) * Ci] = (Gr0 + 2.f * (Gr1 * cm[xx] - Gi1 * sm[xx])) * (1.f / 9.f);
    }
}

// ---------------- fused prep: cvt+gap | zero gap2 | synth1 | synth2 ----------------
// block ranges: [0,2048) cvt_gap, [2048,2064) zero, [2064,2576) synth1, [2576,3600) synth2
__global__ void prep_kernel(const float* __restrict__ x, __half* __restrict__ xh,
                            float* __restrict__ gap1, float* __restrict__ gap2,
                            const float* __restrict__ w1fr, const float* __restrict__ w1fi,
                            float* __restrict__ bank1,
                            const float* __restrict__ w2fr, const float* __restrict__ w2fi,
                            float* __restrict__ bank2) {
    const int bid = blockIdx.x;
    if (bid < 2048) {
        const size_t base = (size_t)bid * (HW * HW);
        const float4* p = reinterpret_cast<const float4*>(x + base);
        uint2* q = reinterpret_cast<uint2*>(xh + base);
        float s = 0.f;
        for (int i = threadIdx.x; i < HW * HW / 4; i += 256) {
            float4 v = p[i];
            s += (v.x + v.y) + (v.z + v.w);
            __half2 h0 = __floats2half2_rn(v.x, v.y);
            __half2 h1 = __floats2half2_rn(v.z, v.w);
            uint2 u;
            u.x = *reinterpret_cast<uint32_t*>(&h0);
            u.y = *reinterpret_cast<uint32_t*>(&h1);
            q[i] = u;
        }
        __shared__ float red[8];
        for (int o = 16; o; o >>= 1) s += __shfl_down_sync(0xffffffffu, s, o);
        if ((threadIdx.x & 31) == 0) red[threadIdx.x >> 5] = s;
        __syncthreads();
        if (threadIdx.x < 8) {
            s = red[threadIdx.x];
            for (int o = 4; o; o >>= 1) s += __shfl_down_sync(0xffu, s, o);
            if (threadIdx.x == 0) gap1[bid] = s * (1.f / (HW * HW));
        }
    } else if (bid < 2064) {
        int i = (bid - 2048) * 256 + threadIdx.x;
        if (i < NB * 256) gap2[i] = 0.f;
    } else if (bid < 2576) {
        int idx = (bid - 2064) * 256 + threadIdx.x;
        if (idx < 4 * CO * 128) synth_body(w1fr, w1fi, bank1, 128, idx);
    } else {
        int idx = (bid - 2576) * 256 + threadIdx.x;
        if (idx < 4 * CO * 256) synth_body(w2fr, w2fi, bank2, 256, idx);
    }
}

// ---------------- GAP -> MLP -> softmax ----------------
__global__ void attn_kernel(const float* __restrict__ gap, const float* __restrict__ w1,
                            const float* __restrict__ b1, const float* __restrict__ w2,
                            const float* __restrict__ b2, float* __restrict__ attn,
                            int C, int Hd) {
    __shared__ float gs[256];
    __shared__ float hbuf[64];
    int b = blockIdx.x;
    for (int i = threadIdx.x; i < C; i += blockDim.x) gs[i] = gap[b * C + i];
    __syncthreads();
    for (int j = threadIdx.x; j < Hd; j += blockDim.x) {
        float s = b1[j];
        for (int c = 0; c < C; c++) s += gs[c] * w1[c * Hd + j];
        hbuf[j] = fmaxf(s, 0.f);
    }
    __syncthreads();
    if (threadIdx.x == 0) {
        float l[4];
        float m = -1e30f;
        for (int k = 0; k < 4; k++) {
            float s = b2[k];
            for (int j = 0; j < Hd; j++) s += hbuf[j] * w2[j * 4 + k];
            l[k] = s; m = fmaxf(m, s);
        }
        float sum = 0.f;
        for (int k = 0; k < 4; k++) { l[k] = expf(l[k] - m); sum += l[k]; }
        float inv = 1.f / sum;
        for (int k = 0; k < 4; k++) attn[b * 4 + k] = l[k] * inv;
    }
}

// ---------------- weight mix ----------------
__global__ void mix_kernel(const float* __restrict__ bank, const float* __restrict__ attn,
                           __half* __restrict__ wmix, int K) {
    int total = NB * CO * (K / 2);
    int i = blockIdx.x * blockDim.x + threadIdx.x;
    if (i >= total) return;
    int perb = CO * (K / 2);
    int b = i / perb;
    int r = (i - b * perb) * 2;           // co*K + k  (tap-major k)
    float a0 = attn[b * 4 + 0], a1 = attn[b * 4 + 1];
    float a2 = attn[b * 4 + 2], a3 = attn[b * 4 + 3];
    int plane = CO * K;
    const float* p = bank + r;
    float x0 = a0 * p[0] + a1 * p[plane] + a2 * p[2 * plane] + a3 * p[3 * plane];
    float x1 = a0 * p[1] + a1 * p[plane + 1] + a2 * p[2 * plane + 1] + a3 * p[3 * plane + 1];
    reinterpret_cast<__half2*>(wmix)[i] = __floats2half2_rn(x0, x1);
}

// ---------------- HMMA implicit-GEMM conv ----------------
// CTA = (b, 128-co half, 2 rows = 256 px). K chunks of 64, tap-major.
// A quad-buffered via cp.async; B triple-buffered, register-staged. One sync per chunk.
// Inside each kstep: B fragments double-buffered (ldmatrix pipelined under MMAs).
#define SA 72                 // halves per A row (144B, conflict-free)
#define SB 264                // halves per B row (528B, conflict-free)
#define ABYTES (128 * SA * 2)
#define BBYTES (64 * SB * 2)
#define SMTOT  (4 * ABYTES + 3 * BBYTES)

template<int CIN, bool OUT_HALF, bool GAP_OUT>
__global__ void __launch_bounds__(512, 1)
conv_hmma_kernel(const __half* __restrict__ xh, const __half* __restrict__ wmix,
                 const float* __restrict__ bias, void* __restrict__ outv,
                 float* __restrict__ gapout) {
    constexpr int K   = CIN * 9;
    constexpr int NCH = K / 64;
    constexpr int TPC = CIN / 64;       // chunks per tap

    extern __shared__ __align__(16) char smem[];
    const uint32_t sbase = smem_u32(smem);
    const uint32_t sbB   = sbase + 4 * ABYTES;
    __half* sBp = reinterpret_cast<__half*>(smem + 4 * ABYTES);

    const int tid = threadIdx.x, wid = tid >> 5, lane = tid & 31;
    const int b   = blockIdx.z;
    const int co0 = blockIdx.y * 128;
    const int y0  = blockIdx.x * 2;
    const int wr = wid & 3, wc = wid >> 2;

    const __half* xb = xh + (size_t)b * CIN * HW * HW;
    const __half* wb = wmix + (size_t)(b * 256 + co0) * K;

    float d[2][8][4];
#pragma unroll
    for (int mt = 0; mt < 2; mt++)
#pragma unroll
        for (int nt = 0; nt < 8; nt++)
#pragma unroll
            for (int q = 0; q < 4; q++) d[mt][nt][q] = 0.f;

    // A cp.async mapping: thread -> rows (tid>>3, +64), seg tid&7 (8 halves)
    const int arow = tid >> 3, aseg = tid & 7;
    const __half* asrc0 = wb + (size_t)arow * K + aseg * 8;
    const uint32_t adst0 = sbase + (uint32_t)(arow * SA + aseg * 8) * 2;

    // B task mapping: 8 tasks/warp: kl = id>>1, yr = id&1
    const int bid0 = wid * 8;

    uint2 bS[8];

    auto ldg_b = [&](int cc) {
        const int tap = cc / TPC;
        const int dy  = tap / 3;
        const int ci0 = (cc % TPC) * 64;
#pragma unroll
        for (int t = 0; t < 8; t++) {
            int id = bid0 + t, kl = id >> 1, yr = id & 1;
            int gy = y0 + yr + dy - 1;
            uint2 v = make_uint2(0u, 0u);
            if ((unsigned)gy < 128u)
                v = __ldg(reinterpret_cast<const uint2*>(
                        xb + ((size_t)(ci0 + kl) * HW + gy) * HW) + lane);
            bS[t] = v;
        }
    };
    auto store_b = [&](int cc) {
        const int dx = (cc / TPC) % 3;
        __half* dst = sBp + (cc % 3) * (BBYTES / 2);
#pragma unroll
        for (int t = 0; t < 8; t++) {
            int id = bid0 + t, kl = id >> 1, yr = id & 1;
            uint2 u = bS[t], o;
            if (dx == 1) {
                o = u;
            } else if (dx == 0) {
                uint32_t prev = __shfl_up_sync(0xffffffffu, u.y, 1);
                o.x = __byte_perm(prev, u.x, 0x5432);
                o.y = __byte_perm(u.x, u.y, 0x5432);
                if (lane == 0) o.x = u.x << 16;
            } else {
                uint32_t nxt = __shfl_down_sync(0xffffffffu, u.x, 1);
                o.x = __byte_perm(u.x, u.y, 0x5432);
                o.y = __byte_perm(u.y, nxt, 0x5432);
                if (lane == 31) o.y = u.y >> 16;
            }
            *reinterpret_cast<uint2*>(dst + kl * SB + yr * 128 + lane * 4) = o;
        }
    };
    auto cpa_a = [&](int cc) {
        const __half* asrc = asrc0 + cc * 64;
        const uint32_t adst = adst0 + (cc & 3) * ABYTES;
        cp_async16(adst, asrc);
        cp_async16(adst + 64 * SA * 2, asrc + (size_t)64 * K);
    };

    // one k16-step of chunk c; B fragments double-buffered under the MMAs
    auto kstep = [&](int c, int ks) {
        const uint32_t sa = sbase + (c & 3) * ABYTES;
        const uint32_t sb = sbB + (c % 3) * BBYTES;
        uint32_t a[2][4];
#pragma unroll
        for (int mt = 0; mt < 2; mt++) {
            uint32_t addr = sa + (uint32_t)((wr * 32 + mt * 16 + (lane & 15)) * SA
                                            + ks * 16 + (lane >> 4) * 8) * 2;
            ldsm_x4(a[mt][0], a[mt][1], a[mt][2], a[mt][3], addr);
        }
        uint32_t bf[2][4];
        const uint32_t brow = sb + (uint32_t)((ks * 16 + (lane & 15)) * SB
                                              + wc * 64 + (lane >> 4) * 8) * 2;
        ldsm_x4_t(bf[0][0], bf[0][1], bf[0][2], bf[0][3], brow);
#pragma unroll
        for (int ng = 0; ng < 4; ng++) {
            if (ng < 3)
                ldsm_x4_t(bf[(ng + 1) & 1][0], bf[(ng + 1) & 1][1],
                          bf[(ng + 1) & 1][2], bf[(ng + 1) & 1][3],
                          brow + (uint32_t)((ng + 1) * 16) * 2);
            const uint32_t* f = bf[ng & 1];
#pragma unroll
            for (int mt = 0; mt < 2; mt++) {
                mma16816(d[mt][ng * 2 + 0], a[mt], f[0], f[1]);
                mma16816(d[mt][ng * 2 + 1], a[mt], f[2], f[3]);
            }
        }
    };

    // ---- prologue ----
    cpa_a(0); CP_COMMIT();
    cpa_a(1); CP_COMMIT();
    ldg_b(0);
    store_b(0);
    ldg_b(1);
    CP_WAIT(1);
    __syncthreads();

    for (int c = 0; c < NCH; c++) {
        kstep(c, 0);
        if (c + 1 < NCH) store_b(c + 1);       // writes buf (c+1)%3, readers on c%3
        kstep(c, 1);
        if (c + 2 < NCH) ldg_b(c + 2);         // after store_b consumed bS (WAR in order)
        kstep(c, 2);
        if (c + 2 < NCH) cpa_a(c + 2);
        CP_COMMIT();
        kstep(c, 3);
        CP_WAIT(1);                            // A(c+1) landed
        __syncthreads();                       // B(c+1) stores visible; buf c%3 free
    }

    // ---- epilogue: bias + relu + stores (+ optional fused GAP of this layer's output) ----
#pragma unroll
    for (int mt = 0; mt < 2; mt++) {
        int corow = co0 + wr * 32 + mt * 16 + (lane >> 2);
#pragma unroll
        for (int h = 0; h < 2; h++) {
            int co = corow + h * 8;
            float bv = bias[co];
            size_t base = ((size_t)(b * 256 + co) * HW + y0) * HW;
            float gs = 0.f;
#pragma unroll
            for (int nt = 0; nt < 8; nt++) {
                int px = wc * 64 + nt * 8 + (lane & 3) * 2;
                int yr = px >> 7, xx = px & 127;
                float vx = fmaxf(d[mt][nt][h * 2 + 0] + bv, 0.f);
                float vy = fmaxf(d[mt][nt][h * 2 + 1] + bv, 0.f);
                if (GAP_OUT) gs += vx + vy;
                if (OUT_HALF) {
                    __half2 hv = __floats2half2_rn(vx, vy);
                    *reinterpret_cast<__half2*>((__half*)outv + base + yr * HW + xx) = hv;
                } else {
                    float2 fv = make_float2(vx, vy);
                    *reinterpret_cast<float2*>((float*)outv + base + yr * HW + xx) = fv;
                }
            }
            if (GAP_OUT) {
                gs += __shfl_xor_sync(0xffffffffu, gs, 1);
                gs += __shfl_xor_sync(0xffffffffu, gs, 2);
                if ((lane & 3) == 0)
                    atomicAdd(&gapout[b * 256 + co], gs * (1.f / (HW * HW)));
            }
        }
    }
}

// ---------------- launch ----------------
extern "C" void kernel_launch(void* const* d_in, const int* in_sizes, int n_in,
                              void* d_out, int out_size) {
    const float* x    = (const float*)d_in[0];
    const float* w1fr = (const float*)d_in[1];
    const float* w1fi = (const float*)d_in[2];
    const float* b1   = (const float*)d_in[3];
    const float* a1w1 = (const float*)d_in[4];
    const float* a1b1 = (const float*)d_in[5];
    const float* a1w2 = (const float*)d_in[6];
    const float* a1b2 = (const float*)d_in[7];
    const float* w2fr = (const float*)d_in[8];
    const float* w2fi = (const float*)d_in[9];
    const float* b2   = (const float*)d_in[10];
    const float* a2w1 = (const float*)d_in[11];
    const float* a2b1 = (const float*)d_in[12];
    const float* a2w2 = (const float*)d_in[13];
    const float* a2b2 = (const float*)d_in[14];
    float* out = (float*)d_out;

    float *bank1, *bank2, *gap1, *gap2, *attnb;
    __half *wm1, *wm2, *xhb, *yhb;
    cudaGetSymbolAddress((void**)&bank1, g_bank1);
    cudaGetSymbolAddress((void**)&bank2, g_bank2);
    cudaGetSymbolAddress((void**)&gap1,  g_gap1);
    cudaGetSymbolAddress((void**)&gap2,  g_gap2);
    cudaGetSymbolAddress((void**)&attnb, g_attn);
    cudaGetSymbolAddress((void**)&wm1,   g_wmix1);
    cudaGetSymbolAddress((void**)&wm2,   g_wmix2);
    cudaGetSymbolAddress((void**)&xhb,   g_xh);
    cudaGetSymbolAddress((void**)&yhb,   g_yh);

    cudaFuncSetAttribute(conv_hmma_kernel<128, true, true>,
                         cudaFuncAttributeMaxDynamicSharedMemorySize, SMTOT);
    cudaFuncSetAttribute(conv_hmma_kernel<256, false, false>,
                         cudaFuncAttributeMaxDynamicSharedMemorySize, SMTOT);

    // Launch order: conv1 is launch index 3 (the one ncu has been capturing).
    prep_kernel<<<3600, 256>>>(x, xhb, gap1, gap2,
                               w1fr, w1fi, bank1, w2fr, w2fi, bank2);                // 0
    attn_kernel<<<NB, 64>>>(gap1, a1w1, a1b1, a1w2, a1b2, attnb, 128, 32);           // 1
    {
        int K = 128 * 9;
        int total = NB * CO * (K / 2);
        mix_kernel<<<(total + 255) / 256, 256>>>(bank1, attnb, wm1, K);              // 2
    }
    conv_hmma_kernel<128, true, true><<<dim3(64, 2, NB), 512, SMTOT>>>(xhb, wm1, b1, yhb, gap2);  // 3

    attn_kernel<<<NB, 64>>>(gap2, a2w1, a2b1, a2w2, a2b2, attnb, 256, 64);           // 4
    {
        int K = 256 * 9;
        int total = NB * CO * (K / 2);
        mix_kernel<<<(total + 255) / 256, 256>>>(bank2, attnb, wm2, K);              // 5
    }
    conv_hmma_kernel<256, false, false><<<dim3(64, 2, NB), 512, SMTOT>>>(yhb, wm2, b2, out, nullptr);  // 6
}